// round 1
// baseline (speedup 1.0000x reference)
#include <cuda_runtime.h>
#include <math.h>

// Problem constants
#define EE  4      // experts
#define BB  32     // batch
#define HH  7
#define LL  49     // H*W
#define DD  512    // dim
#define C2  1024   // 2*dim
#define RR  32     // DT_RANK
#define NS  16     // N_STATE
#define KDn 4      // directions

// ---------------- scratch (device globals; no allocation allowed) ----------
__device__ float g_xz[EE*BB*LL*C2];          // in_proj output [e][b][l][c]
__device__ float g_xs[EE*BB*KDn*LL*DD];      // 4-direction scan inputs [e][b][k][l][d]
__device__ float g_dt[EE*BB*KDn*LL*DD];      // softplus(dt) [e][b][k][l][d]
__device__ float g_ys[EE*BB*KDn*LL*DD];      // scan outputs [e][b][k][l][d]
__device__ float g_Bm[EE*BB*KDn*LL*NS];      // B matrices [e][b][k][l][n]
__device__ float g_Cm[EE*BB*KDn*LL*NS];      // C matrices
__device__ float g_raw[BB*EE];
__device__ float g_aux;
__device__ int   g_topi[BB*2];
__device__ float g_topv[BB*2];
__device__ float g_allout[EE*BB*DD];

// ---------------- f32x2 packed FMA helpers (sm_103a) -----------------------
__device__ __forceinline__ unsigned long long pk2(float lo, float hi){
    unsigned long long r;
    asm("mov.b64 %0, {%1, %2};" : "=l"(r) : "f"(lo), "f"(hi));
    return r;
}
__device__ __forceinline__ void fma2(unsigned long long& d, unsigned long long a, unsigned long long b){
    asm("fma.rn.f32x2 %0, %1, %2, %0;" : "+l"(d) : "l"(a), "l"(b));
}
__device__ __forceinline__ void upk2(unsigned long long v, float& lo, float& hi){
    asm("mov.b64 {%0, %1}, %2;" : "=f"(lo), "=f"(hi) : "l"(v));
}

// ---------------- K1: gate logits + softmax per batch ----------------------
__global__ void k_gate(const float* __restrict__ x, const float* __restrict__ wg,
                       const float* __restrict__ bg){
    int b = blockIdx.x, tid = threadIdx.x;           // 512 threads, tid = channel
    const float* xb = x + (size_t)b*LL*DD + tid;
    float s = 0.f;
    #pragma unroll 7
    for (int l = 0; l < LL; l++) s += xb[l*DD];
    s *= (1.f/49.f);
    float p0 = s*wg[tid*EE+0], p1 = s*wg[tid*EE+1];
    float p2 = s*wg[tid*EE+2], p3 = s*wg[tid*EE+3];
    #pragma unroll
    for (int o = 16; o; o >>= 1){
        p0 += __shfl_xor_sync(0xffffffffu, p0, o);
        p1 += __shfl_xor_sync(0xffffffffu, p1, o);
        p2 += __shfl_xor_sync(0xffffffffu, p2, o);
        p3 += __shfl_xor_sync(0xffffffffu, p3, o);
    }
    __shared__ float sp[16][4];
    int w = tid >> 5, lane = tid & 31;
    if (lane == 0){ sp[w][0]=p0; sp[w][1]=p1; sp[w][2]=p2; sp[w][3]=p3; }
    __syncthreads();
    if (tid == 0){
        float lg[4];
        for (int e = 0; e < 4; e++){
            float a = bg[e];
            for (int ww = 0; ww < 16; ww++) a += sp[ww][e];
            lg[e] = a;
        }
        float m = fmaxf(fmaxf(lg[0],lg[1]), fmaxf(lg[2],lg[3]));
        float ex[4], se = 0.f;
        for (int e = 0; e < 4; e++){ ex[e] = expf(lg[e]-m); se += ex[e]; }
        for (int e = 0; e < 4; e++) g_raw[b*4+e] = ex[e]/se;
    }
}

// ---------------- K2: top-k, mask, denom, aux loss, gate scores ------------
__global__ void k_gatefin(){
    __shared__ float sraw[32][4];
    __shared__ float smask[32][4];
    __shared__ float sden[4];
    int b = threadIdx.x;  // 32 threads
    float r[4];
    #pragma unroll
    for (int e = 0; e < 4; e++){ r[e] = g_raw[b*4+e]; sraw[b][e] = r[e]; }
    int i0 = 0; float m0 = r[0];
    #pragma unroll
    for (int e = 1; e < 4; e++) if (r[e] > m0){ m0 = r[e]; i0 = e; }
    int i1 = -1; float m1 = -1e30f;
    #pragma unroll
    for (int e = 0; e < 4; e++) if (e != i0 && r[e] > m1){ m1 = r[e]; i1 = e; }
    #pragma unroll
    for (int e = 0; e < 4; e++) smask[b][e] = (e==i0 || e==i1) ? 1.f : 0.f;
    __syncthreads();
    if (b == 0){
        float aux = 0.f;
        for (int e = 0; e < 4; e++){
            float ds = 0.f, imp = 0.f, ld = 0.f;
            for (int bb = 0; bb < 32; bb++){
                ds  += sraw[bb][e]*smask[bb][e];
                imp += sraw[bb][e];
                ld  += smask[bb][e];
            }
            sden[e] = ds + 1e-6f;
            imp *= (1.f/32.f); ld *= (1.f/32.f);
            aux += (ld-imp)*(ld-imp);
        }
        g_aux = 0.01f * aux * 0.25f;
    }
    __syncthreads();
    const float cap = 40.f;   // int(1.25*32)
    float s0 = r[i0]*cap/sden[i0];
    float s1 = r[i1]*cap/sden[i1];
    int a0 = i0, a1 = i1; float v0 = s0, v1 = s1;
    if (v1 > v0 || (v1 == v0 && a1 < a0)){
        int t = a0; a0 = a1; a1 = t;
        float tv = v0; v0 = v1; v1 = tv;
    }
    g_topi[b*2] = a0; g_topi[b*2+1] = a1;
    g_topv[b*2] = v0; g_topv[b*2+1] = v1;
}

// ---------------- K3: in_proj GEMM (49x512 @ 512x1024) per (e,b) -----------
// Block = (b,e), 256 threads; thread tile 17(l) x 4(c); f32x2 packed FMA.
__global__ void __launch_bounds__(256, 1)
k_inproj(const float* __restrict__ x, const float* __restrict__ Wi,
         const float* __restrict__ bi){
    extern __shared__ float sxh[];     // 51*512 floats (rows 49,50 zero pad)
    int b = blockIdx.x, e = blockIdx.y, tid = threadIdx.x;
    const float* xb = x + (size_t)b*LL*DD;
    for (int i = tid; i < LL*DD; i += 256) sxh[i] = xb[i];
    for (int i = LL*DD + tid; i < 51*DD; i += 256) sxh[i] = 0.f;
    __syncthreads();
    const float* We = Wi + (size_t)e*DD*C2;
    int c0 = tid*4;
    float* xzout = g_xz + (size_t)(e*BB+b)*LL*C2;
    float4 bia = *(const float4*)(bi + e*C2 + c0);
    for (int lt = 0; lt < 3; lt++){
        int base = lt*17;
        unsigned long long acc[34];
        #pragma unroll
        for (int i = 0; i < 34; i++) acc[i] = 0ull;
        #pragma unroll 2
        for (int kk = 0; kk < DD; kk++){
            float4 w = *(const float4*)(We + (size_t)kk*C2 + c0);
            unsigned long long wa = pk2(w.x, w.y);
            unsigned long long wb = pk2(w.z, w.w);
            const float* xr = sxh + base*DD + kk;
            #pragma unroll
            for (int i = 0; i < 17; i++){
                float xk = xr[i*DD];
                unsigned long long xp = pk2(xk, xk);
                fma2(acc[2*i],   wa, xp);
                fma2(acc[2*i+1], wb, xp);
            }
        }
        #pragma unroll
        for (int i = 0; i < 17; i++){
            int l = base + i;
            if (l < LL){
                float r0,r1,r2,r3;
                upk2(acc[2*i],   r0, r1);
                upk2(acc[2*i+1], r2, r3);
                float4 o = make_float4(r0+bia.x, r1+bia.y, r2+bia.z, r3+bia.w);
                *(float4*)(xzout + (size_t)l*C2 + c0) = o;
            }
        }
    }
}

// ---------------- K4: depthwise 3x3 conv + silu + 4-direction scatter ------
__global__ void k_conv(const float* __restrict__ cw, const float* __restrict__ cb){
    int b = blockIdx.x, e = blockIdx.y, d = threadIdx.x;   // 512 threads
    const float* xin = g_xz + (size_t)(e*BB+b)*LL*C2 + d;  // channel 0..511 = xin
    float w9[9];
    #pragma unroll
    for (int t = 0; t < 9; t++) w9[t] = cw[(e*DD+d)*9 + t];
    float bias = cb[e*DD+d];
    float* xsb = g_xs + (size_t)(e*BB+b)*KDn*LL*DD;
    for (int i = 0; i < 7; i++){
        for (int j = 0; j < 7; j++){
            float a = bias;
            #pragma unroll
            for (int di = 0; di < 3; di++){
                int ii = i + di - 1;
                if (ii < 0 || ii > 6) continue;
                #pragma unroll
                for (int dj = 0; dj < 3; dj++){
                    int jj = j + dj - 1;
                    if (jj < 0 || jj > 6) continue;
                    a += xin[(ii*7+jj)*C2] * w9[di*3+dj];
                }
            }
            float v = a / (1.f + __expf(-a));   // silu
            int l  = i*7 + j;
            int lv = j*7 + i;
            xsb[(0*LL + l       )*DD + d] = v;
            xsb[(1*LL + (48-l)  )*DD + d] = v;
            xsb[(2*LL + lv      )*DD + d] = v;
            xsb[(3*LL + (48-lv) )*DD + d] = v;
        }
    }
}

// ---------------- K5: x_dbl projection + dt projection + softplus ----------
// Block per (e,b,k), 256 threads.
__global__ void k_xdbl(const float* __restrict__ xpw_, const float* __restrict__ dtw_,
                       const float* __restrict__ dtb_){
    int idx = blockIdx.x;
    int k = idx & 3, b = (idx >> 2) & 31, e = idx >> 7;
    int tid = threadIdx.x;
    const float* xsrow = g_xs + (size_t)((e*BB+b)*KDn + k)*LL*DD;
    const float* xpw = xpw_ + (size_t)((e*KDn+k)*64)*DD;   // [c][d]
    const float* dtw = dtw_ + (size_t)((e*KDn+k)*DD)*RR;   // [d][r]
    const float* dtb = dtb_ + (e*KDn+k)*DD;
    float* dtout = g_dt + (size_t)((e*BB+b)*KDn + k)*LL*DD;
    float* Bout  = g_Bm + (size_t)((e*BB+b)*KDn + k)*LL*NS;
    float* Cout  = g_Cm + (size_t)((e*BB+b)*KDn + k)*LL*NS;
    __shared__ float sx[DD];
    __shared__ float sdt[RR];
    int c = tid >> 2, part = tid & 3;
    for (int l = 0; l < LL; l++){
        sx[tid]       = xsrow[l*DD + tid];
        sx[tid + 256] = xsrow[l*DD + tid + 256];
        __syncthreads();
        // 64 output channels c, 4 threads each (128 elems per thread)
        {
            const float* wrow = xpw + (size_t)c*DD + part*128;
            const float* xp = sx + part*128;
            float s = 0.f;
            #pragma unroll 8
            for (int t = 0; t < 128; t++) s += xp[t]*wrow[t];
            s += __shfl_xor_sync(0xffffffffu, s, 1);
            s += __shfl_xor_sync(0xffffffffu, s, 2);
            if (part == 0){
                if (c < 32)      sdt[c] = s;
                else if (c < 48) Bout[l*NS + (c-32)] = s;
                else             Cout[l*NS + (c-48)] = s;
            }
        }
        __syncthreads();
        // dt projection + softplus, 2 d per thread
        for (int dd = tid; dd < DD; dd += 256){
            float a = dtb[dd];
            const float* wr = dtw + (size_t)dd*RR;
            #pragma unroll
            for (int rr = 0; rr < RR; rr++) a += sdt[rr]*wr[rr];
            float sp = fmaxf(a, 0.f) + log1pf(__expf(-fabsf(a)));
            dtout[l*DD + dd] = sp;
        }
        __syncthreads();
    }
}

// ---------------- K6: selective scan over L=49 ------------------------------
// Block per (e,b,k), 512 threads (thread = channel d), h[16] in registers.
__global__ void k_scan(const float* __restrict__ alog_, const float* __restrict__ ds_){
    int idx = blockIdx.x;
    int k = idx & 3, b = (idx >> 2) & 31, e = idx >> 7;
    int d = threadIdx.x;
    const float* al = alog_ + ((size_t)((e*KDn+k)*DD) + d)*NS;
    float A[NS];
    #pragma unroll
    for (int n = 0; n < NS; n++) A[n] = -__expf(al[n]);
    float Dd = ds_[(e*KDn+k)*DD + d];
    size_t base = (size_t)((e*BB+b)*KDn + k)*LL*DD;
    size_t bbc  = (size_t)((e*BB+b)*KDn + k)*LL*NS;
    float h[NS];
    #pragma unroll
    for (int n = 0; n < NS; n++) h[n] = 0.f;
    __shared__ float sB[NS], sC[NS];
    for (int l = 0; l < LL; l++){
        if (d < NS)            sB[d]      = g_Bm[bbc + l*NS + d];
        else if (d < 2*NS)     sC[d-NS]   = g_Cm[bbc + l*NS + (d-NS)];
        __syncthreads();
        float dt = g_dt[base + l*DD + d];
        float xv = g_xs[base + l*DD + d];
        float dx = dt*xv;
        float y = 0.f;
        #pragma unroll
        for (int n = 0; n < NS; n++){
            h[n] = h[n]*__expf(dt*A[n]) + dx*sB[n];
            y += h[n]*sC[n];
        }
        g_ys[base + l*DD + d] = y + Dd*xv;
        __syncthreads();
    }
}

// ---------------- block reduction (sum, sumsq) over 512 threads ------------
__device__ __forceinline__ float2 blockReduce2(float a, float b){
    __shared__ float sa[16], sb[16];
    __shared__ float2 res;
    int lane = threadIdx.x & 31, w = threadIdx.x >> 5;
    #pragma unroll
    for (int o = 16; o; o >>= 1){
        a += __shfl_xor_sync(0xffffffffu, a, o);
        b += __shfl_xor_sync(0xffffffffu, b, o);
    }
    __syncthreads();           // guard against previous call's readers
    if (lane == 0){ sa[w] = a; sb[w] = b; }
    __syncthreads();
    if (w == 0){
        a = (lane < 16) ? sa[lane] : 0.f;
        b = (lane < 16) ? sb[lane] : 0.f;
        #pragma unroll
        for (int o = 8; o; o >>= 1){
            a += __shfl_xor_sync(0xffffffffu, a, o);
            b += __shfl_xor_sync(0xffffffffu, b, o);
        }
        if (lane == 0){ res.x = a; res.y = b; }
    }
    __syncthreads();
    return res;
}

// ---------------- K7: combine directions + LN + silu(z) gate + pool + LN ---
__global__ void k_combine(const float* __restrict__ og_, const float* __restrict__ ob_,
                          const float* __restrict__ ng_, const float* __restrict__ nb_){
    int b = blockIdx.x, e = blockIdx.y, d = threadIdx.x;   // 512 threads
    size_t yb = (size_t)(e*BB+b)*KDn*LL*DD;
    const float* zrow = g_xz + (size_t)(e*BB+b)*LL*C2 + DD;  // z channels
    float og = og_[e*DD+d], ob = ob_[e*DD+d];
    float pooled = 0.f;
    for (int l = 0; l < LL; l++){
        int i = l/7, j = l - 7*i;
        int lv = j*7 + i;
        float v = g_ys[yb + (0*LL + l       )*DD + d]
                + g_ys[yb + (1*LL + (48-l)  )*DD + d]
                + g_ys[yb + (2*LL + lv      )*DD + d]
                + g_ys[yb + (3*LL + (48-lv) )*DD + d];
        float2 ss = blockReduce2(v, v*v);
        float mu = ss.x*(1.f/512.f);
        float var = ss.y*(1.f/512.f) - mu*mu;
        float rs = rsqrtf(var + 1e-5f);
        float yn = (v - mu)*rs*og + ob;
        float z = zrow[l*C2 + d];
        pooled += yn * (z / (1.f + __expf(-z)));
    }
    pooled *= (1.f/49.f);
    float2 ss = blockReduce2(pooled, pooled*pooled);
    float mu = ss.x*(1.f/512.f);
    float var = ss.y*(1.f/512.f) - mu*mu;
    float rs = rsqrtf(var + 1e-5f);
    g_allout[(e*BB+b)*DD + d] = (pooled - mu)*rs*ng_[e*DD+d] + nb_[e*DD+d];
}

// ---------------- K8: mixture + aux loss output -----------------------------
__global__ void k_mix(float* __restrict__ out, int out_size){
    int b = blockIdx.x, d = threadIdx.x;
    int   a0 = g_topi[b*2], a1 = g_topi[b*2+1];
    float v0 = g_topv[b*2], v1 = g_topv[b*2+1];
    out[b*DD + d] = v0*g_allout[(a0*BB+b)*DD + d] + v1*g_allout[(a1*BB+b)*DD + d];
    if (b == 0 && d == 0 && out_size > BB*DD) out[BB*DD] = g_aux;
}

// ---------------- launch ----------------------------------------------------
extern "C" void kernel_launch(void* const* d_in, const int* in_sizes, int n_in,
                              void* d_out, int out_size){
    const float* x    = (const float*)d_in[0];
    const float* wg   = (const float*)d_in[1];
    const float* bg   = (const float*)d_in[2];
    const float* ipw  = (const float*)d_in[3];
    const float* ipb  = (const float*)d_in[4];
    const float* cw   = (const float*)d_in[5];
    const float* cb   = (const float*)d_in[6];
    const float* xpw  = (const float*)d_in[7];
    const float* dtw  = (const float*)d_in[8];
    const float* dtb  = (const float*)d_in[9];
    const float* alog = (const float*)d_in[10];
    const float* ds   = (const float*)d_in[11];
    const float* ong  = (const float*)d_in[12];
    const float* onb  = (const float*)d_in[13];
    const float* ng   = (const float*)d_in[14];
    const float* nb   = (const float*)d_in[15];
    float* out = (float*)d_out;

    const int smem_inproj = 51*DD*sizeof(float);   // 104448 B
    cudaFuncSetAttribute(k_inproj, cudaFuncAttributeMaxDynamicSharedMemorySize, smem_inproj);

    k_gate   <<<32, 512>>>(x, wg, bg);
    k_gatefin<<<1, 32>>>();
    k_inproj <<<dim3(32,4), 256, smem_inproj>>>(x, ipw, ipb);
    k_conv   <<<dim3(32,4), 512>>>(cw, cb);
    k_xdbl   <<<512, 256>>>(xpw, dtw, dtb);
    k_scan   <<<512, 512>>>(alog, ds);
    k_combine<<<dim3(32,4), 512>>>(ong, onb, ng, nb);
    k_mix    <<<32, 512>>>(out, out_size);
}

// round 2
// speedup vs baseline: 6.4236x; 6.4236x over previous
#include <cuda_runtime.h>
#include <math.h>

// Problem constants
#define EE  4      // experts
#define BB  32     // batch
#define HH  7
#define LL  49     // H*W
#define DD  512    // dim
#define C2  1024   // 2*dim
#define RR  32     // DT_RANK
#define NS  16     // N_STATE
#define KDn 4      // directions

// ---------------- scratch (device globals; no allocation allowed) ----------
__device__ float g_xz[EE*BB*LL*C2];          // in_proj output [e][b][l][c]
__device__ float g_xs[EE*BB*KDn*LL*DD];      // 4-direction scan inputs [e][b][k][l][d]
__device__ float g_dt[EE*BB*KDn*LL*DD];      // softplus(dt) [e][b][k][l][d]
__device__ float g_ys[EE*BB*KDn*LL*DD];      // scan outputs [e][b][k][l][d]
__device__ float g_Bm[EE*BB*KDn*LL*NS];      // B matrices [e][b][k][l][n]
__device__ float g_Cm[EE*BB*KDn*LL*NS];      // C matrices
__device__ float g_raw[BB*EE];
__device__ float g_aux;
__device__ int   g_topi[BB*2];
__device__ float g_topv[BB*2];
__device__ float g_allout[EE*BB*DD];

// ---------------- f32x2 packed FMA helpers (sm_103a) -----------------------
__device__ __forceinline__ unsigned long long pk2(float lo, float hi){
    unsigned long long r;
    asm("mov.b64 %0, {%1, %2};" : "=l"(r) : "f"(lo), "f"(hi));
    return r;
}
__device__ __forceinline__ void fma2(unsigned long long& d, unsigned long long a, unsigned long long b){
    asm("fma.rn.f32x2 %0, %1, %2, %0;" : "+l"(d) : "l"(a), "l"(b));
}
__device__ __forceinline__ void upk2(unsigned long long v, float& lo, float& hi){
    asm("mov.b64 {%0, %1}, %2;" : "=f"(lo), "=f"(hi) : "l"(v));
}

// ---------------- K1: gate logits + softmax per batch ----------------------
__global__ void k_gate(const float* __restrict__ x, const float* __restrict__ wg,
                       const float* __restrict__ bg){
    int b = blockIdx.x, tid = threadIdx.x;           // 512 threads, tid = channel
    const float* xb = x + (size_t)b*LL*DD + tid;
    float s = 0.f;
    #pragma unroll 7
    for (int l = 0; l < LL; l++) s += xb[l*DD];
    s *= (1.f/49.f);
    float p0 = s*wg[tid*EE+0], p1 = s*wg[tid*EE+1];
    float p2 = s*wg[tid*EE+2], p3 = s*wg[tid*EE+3];
    #pragma unroll
    for (int o = 16; o; o >>= 1){
        p0 += __shfl_xor_sync(0xffffffffu, p0, o);
        p1 += __shfl_xor_sync(0xffffffffu, p1, o);
        p2 += __shfl_xor_sync(0xffffffffu, p2, o);
        p3 += __shfl_xor_sync(0xffffffffu, p3, o);
    }
    __shared__ float sp[16][4];
    int w = tid >> 5, lane = tid & 31;
    if (lane == 0){ sp[w][0]=p0; sp[w][1]=p1; sp[w][2]=p2; sp[w][3]=p3; }
    __syncthreads();
    if (tid == 0){
        float lg[4];
        for (int e = 0; e < 4; e++){
            float a = bg[e];
            for (int ww = 0; ww < 16; ww++) a += sp[ww][e];
            lg[e] = a;
        }
        float m = fmaxf(fmaxf(lg[0],lg[1]), fmaxf(lg[2],lg[3]));
        float ex[4], se = 0.f;
        for (int e = 0; e < 4; e++){ ex[e] = expf(lg[e]-m); se += ex[e]; }
        for (int e = 0; e < 4; e++) g_raw[b*4+e] = ex[e]/se;
    }
}

// ---------------- K2: top-k, mask, denom, aux loss, gate scores ------------
__global__ void k_gatefin(){
    __shared__ float sraw[32][4];
    __shared__ float smask[32][4];
    __shared__ float sden[4];
    int b = threadIdx.x;  // 32 threads
    float r[4];
    #pragma unroll
    for (int e = 0; e < 4; e++){ r[e] = g_raw[b*4+e]; sraw[b][e] = r[e]; }
    int i0 = 0; float m0 = r[0];
    #pragma unroll
    for (int e = 1; e < 4; e++) if (r[e] > m0){ m0 = r[e]; i0 = e; }
    int i1 = -1; float m1 = -1e30f;
    #pragma unroll
    for (int e = 0; e < 4; e++) if (e != i0 && r[e] > m1){ m1 = r[e]; i1 = e; }
    #pragma unroll
    for (int e = 0; e < 4; e++) smask[b][e] = (e==i0 || e==i1) ? 1.f : 0.f;
    __syncthreads();
    if (b == 0){
        float aux = 0.f;
        for (int e = 0; e < 4; e++){
            float ds = 0.f, imp = 0.f, ld = 0.f;
            for (int bb = 0; bb < 32; bb++){
                ds  += sraw[bb][e]*smask[bb][e];
                imp += sraw[bb][e];
                ld  += smask[bb][e];
            }
            sden[e] = ds + 1e-6f;
            imp *= (1.f/32.f); ld *= (1.f/32.f);
            aux += (ld-imp)*(ld-imp);
        }
        g_aux = 0.01f * aux * 0.25f;
    }
    __syncthreads();
    const float cap = 40.f;   // int(1.25*32)
    float s0 = r[i0]*cap/sden[i0];
    float s1 = r[i1]*cap/sden[i1];
    int a0 = i0, a1 = i1; float v0 = s0, v1 = s1;
    if (v1 > v0 || (v1 == v0 && a1 < a0)){
        int t = a0; a0 = a1; a1 = t;
        float tv = v0; v0 = v1; v1 = tv;
    }
    g_topi[b*2] = a0; g_topi[b*2+1] = a1;
    g_topv[b*2] = v0; g_topv[b*2+1] = v1;
}

// ---------------- K3: in_proj GEMM (49x512 @ 512x1024) per (e,b) -----------
// Block = (b,e), 256 threads; thread tile 17(l) x 4(c); f32x2 packed FMA.
__global__ void __launch_bounds__(256, 1)
k_inproj(const float* __restrict__ x, const float* __restrict__ Wi,
         const float* __restrict__ bi){
    extern __shared__ float sxh[];     // 51*512 floats (rows 49,50 zero pad)
    int b = blockIdx.x, e = blockIdx.y, tid = threadIdx.x;
    const float* xb = x + (size_t)b*LL*DD;
    for (int i = tid; i < LL*DD; i += 256) sxh[i] = xb[i];
    for (int i = LL*DD + tid; i < 51*DD; i += 256) sxh[i] = 0.f;
    __syncthreads();
    const float* We = Wi + (size_t)e*DD*C2;
    int c0 = tid*4;
    float* xzout = g_xz + (size_t)(e*BB+b)*LL*C2;
    float4 bia = *(const float4*)(bi + e*C2 + c0);
    for (int lt = 0; lt < 3; lt++){
        int base = lt*17;
        unsigned long long acc[34];
        #pragma unroll
        for (int i = 0; i < 34; i++) acc[i] = 0ull;
        #pragma unroll 2
        for (int kk = 0; kk < DD; kk++){
            float4 w = *(const float4*)(We + (size_t)kk*C2 + c0);
            unsigned long long wa = pk2(w.x, w.y);
            unsigned long long wb = pk2(w.z, w.w);
            const float* xr = sxh + base*DD + kk;
            #pragma unroll
            for (int i = 0; i < 17; i++){
                float xk = xr[i*DD];
                unsigned long long xp = pk2(xk, xk);
                fma2(acc[2*i],   wa, xp);
                fma2(acc[2*i+1], wb, xp);
            }
        }
        #pragma unroll
        for (int i = 0; i < 17; i++){
            int l = base + i;
            if (l < LL){
                float r0,r1,r2,r3;
                upk2(acc[2*i],   r0, r1);
                upk2(acc[2*i+1], r2, r3);
                float4 o = make_float4(r0+bia.x, r1+bia.y, r2+bia.z, r3+bia.w);
                *(float4*)(xzout + (size_t)l*C2 + c0) = o;
            }
        }
    }
}

// ---------------- K4: depthwise 3x3 conv + silu + 4-direction scatter ------
// grid (32 b, 4 e, 2 dchunk) x 256 threads
__global__ void k_conv(const float* __restrict__ cw, const float* __restrict__ cb){
    int b = blockIdx.x, e = blockIdx.y;
    int d = blockIdx.z*256 + threadIdx.x;
    const float* xin = g_xz + (size_t)(e*BB+b)*LL*C2 + d;  // channel 0..511 = xin
    float w9[9];
    #pragma unroll
    for (int t = 0; t < 9; t++) w9[t] = cw[(e*DD+d)*9 + t];
    float bias = cb[e*DD+d];
    float* xsb = g_xs + (size_t)(e*BB+b)*KDn*LL*DD;
    for (int i = 0; i < 7; i++){
        for (int j = 0; j < 7; j++){
            float a = bias;
            #pragma unroll
            for (int di = 0; di < 3; di++){
                int ii = i + di - 1;
                if (ii < 0 || ii > 6) continue;
                #pragma unroll
                for (int dj = 0; dj < 3; dj++){
                    int jj = j + dj - 1;
                    if (jj < 0 || jj > 6) continue;
                    a += xin[(ii*7+jj)*C2] * w9[di*3+dj];
                }
            }
            float v = a / (1.f + __expf(-a));   // silu
            int l  = i*7 + j;
            int lv = j*7 + i;
            xsb[(0*LL + l       )*DD + d] = v;
            xsb[(1*LL + (48-l)  )*DD + d] = v;
            xsb[(2*LL + lv      )*DD + d] = v;
            xsb[(3*LL + (48-lv) )*DD + d] = v;
        }
    }
}

// ---------------- K5: x_dbl projection + dt projection + softplus ----------
// Block per (e,b,k), 512 threads. Two-phase smem-resident rewrite:
//   Phase A: sx tile (49x512) + xpw (64 rows, pad stride 514) in smem;
//            thread (lane=c half, warp=l-set) register-accumulates over K.
//   Phase B: smem reused for dtwT (pad 513) + x_dbl dt-rank staging.
#define XDW  514                      // xpw smem row stride (floats)
#define XD_SMEM_BYTES ((LL*DD + 64*XDW)*4)   // 100352 + 131584 = 231936
#define DTW_S 513
__global__ void __launch_bounds__(512, 1)
k_xdbl(const float* __restrict__ xpw_, const float* __restrict__ dtw_,
       const float* __restrict__ dtb_){
    extern __shared__ float sm[];
    float* sx  = sm;                 // LL*DD floats
    float* wsm = sm + LL*DD;         // 64 x XDW
    int idx = blockIdx.x;
    int k = idx & 3, b = (idx >> 2) & 31, e = idx >> 7;
    int tid = threadIdx.x;
    int lane = tid & 31, w = tid >> 5;

    const float* xsrow = g_xs + (size_t)((e*BB+b)*KDn + k)*LL*DD;
    const float* xpw = xpw_ + (size_t)((e*KDn+k)*64)*DD;   // [c][d]
    const float* dtw = dtw_ + (size_t)((e*KDn+k)*DD)*RR;   // [d][r]
    const float* dtb = dtb_ + (e*KDn+k)*DD;
    float* dtout = g_dt + (size_t)((e*BB+b)*KDn + k)*LL*DD;
    float* Bout  = g_Bm + (size_t)((e*BB+b)*KDn + k)*LL*NS;
    float* Cout  = g_Cm + (size_t)((e*BB+b)*KDn + k)*LL*NS;

    // load sx tile (coalesced)
    for (int i = tid; i < LL*DD; i += 512) sx[i] = xsrow[i];
    // load xpw into padded smem rows (coalesced read, conflict-free-ish write)
    for (int i = tid; i < 64*DD; i += 512){
        int c = i >> 9, dd = i & 511;
        wsm[c*XDW + dd] = xpw[i];
    }
    __syncthreads();

    // ---- Phase A: x_dbl[c][l] = sum_d sx[l][d]*w[c][d] ----
    int c0 = lane, c1 = lane + 32;
    float acc0[3] = {0.f,0.f,0.f};
    float acc1[3] = {0.f,0.f,0.f};
    const float* w0p = wsm + c0*XDW;
    const float* w1p = wsm + c1*XDW;
    {
        const float* x0 = sx + (w      )*DD;
        const float* x1 = sx + (w + 16 )*DD;
        const float* x2 = sx + (w + 32 )*DD;
        #pragma unroll 4
        for (int kk = 0; kk < DD; kk += 2){
            float2 wa = *(const float2*)(w0p + kk);
            float2 wb = *(const float2*)(w1p + kk);
            float2 xv;
            xv = *(const float2*)(x0 + kk);
            acc0[0] += xv.x*wa.x + xv.y*wa.y;  acc1[0] += xv.x*wb.x + xv.y*wb.y;
            xv = *(const float2*)(x1 + kk);
            acc0[1] += xv.x*wa.x + xv.y*wa.y;  acc1[1] += xv.x*wb.x + xv.y*wb.y;
            xv = *(const float2*)(x2 + kk);
            acc0[2] += xv.x*wa.x + xv.y*wa.y;  acc1[2] += xv.x*wb.x + xv.y*wb.y;
        }
    }
    // tail: l=48 handled by warp 0 only
    float t0 = 0.f, t1 = 0.f;
    if (w == 0){
        const float* x3 = sx + 48*DD;
        #pragma unroll 4
        for (int kk = 0; kk < DD; kk += 2){
            float2 wa = *(const float2*)(w0p + kk);
            float2 wb = *(const float2*)(w1p + kk);
            float2 xv = *(const float2*)(x3 + kk);
            t0 += xv.x*wa.x + xv.y*wa.y;
            t1 += xv.x*wb.x + xv.y*wb.y;
        }
    }
    __syncthreads();   // done reading sx/wsm; smem now reusable

    // ---- Phase B smem layout (aliased) ----
    float* dtwT = sm;                 // 32 x DTW_S floats (65664 B region)
    float* sdbl = sm + 32*DTW_S;      // 49 x 32 dt-rank staging

    // stage dt-rank results + write B/C to global
    {
        #pragma unroll
        for (int i = 0; i < 3; i++){
            int l = w + 16*i;
            sdbl[l*32 + lane] = acc0[i];
            if (lane < 16) Bout[l*NS + lane]        = acc1[i];
            else           Cout[l*NS + (lane - 16)] = acc1[i];
        }
        if (w == 0){
            sdbl[48*32 + lane] = t0;
            if (lane < 16) Bout[48*NS + lane]        = t1;
            else           Cout[48*NS + (lane - 16)] = t1;
        }
    }
    // load dtw transposed: dtwT[r][dd] = dtw[dd][r]
    for (int i = tid; i < DD*RR; i += 512){
        int dd = i >> 5, r = i & 31;
        dtwT[r*DTW_S + dd] = dtw[i];
    }
    __syncthreads();

    // ---- Phase B: dt[l][dd] = softplus(dtb[dd] + sum_r sdbl[l][r]*dtwT[r][dd])
    int dd = tid;
    float bias = dtb[dd];
    for (int lg = 0; lg < 13; lg++){
        int nl = (lg < 12) ? 4 : 1;    // 12*4 + 1 = 49
        float a0 = bias, a1 = bias, a2 = bias, a3 = bias;
        int l0 = lg*4;
        const float* s0 = sdbl + (l0    )*32;
        const float* s1 = sdbl + (l0 + 1)*32;
        const float* s2 = sdbl + (l0 + 2)*32;
        const float* s3 = sdbl + (l0 + 3)*32;
        if (nl == 4){
            #pragma unroll
            for (int r = 0; r < RR; r++){
                float wv = dtwT[r*DTW_S + dd];
                a0 += s0[r]*wv; a1 += s1[r]*wv; a2 += s2[r]*wv; a3 += s3[r]*wv;
            }
        } else {
            #pragma unroll
            for (int r = 0; r < RR; r++){
                float wv = dtwT[r*DTW_S + dd];
                a0 += s0[r]*wv;
            }
        }
        #pragma unroll
        for (int j = 0; j < 4; j++){
            int l = l0 + j;
            if (j < nl){
                float a = (j==0)?a0:(j==1)?a1:(j==2)?a2:a3;
                float sp = fmaxf(a, 0.f) + log1pf(__expf(-fabsf(a)));
                dtout[l*DD + dd] = sp;
            }
        }
    }
}

// ---------------- K6: selective scan over L=49 ------------------------------
// Block per (e,b,k), 512 threads (thread = channel d), h[16] in registers.
__global__ void k_scan(const float* __restrict__ alog_, const float* __restrict__ ds_){
    int idx = blockIdx.x;
    int k = idx & 3, b = (idx >> 2) & 31, e = idx >> 7;
    int d = threadIdx.x;
    const float4* al = (const float4*)(alog_ + ((size_t)((e*KDn+k)*DD) + d)*NS);
    float A[NS];
    #pragma unroll
    for (int q = 0; q < 4; q++){
        float4 v = al[q];
        A[q*4+0] = -__expf(v.x); A[q*4+1] = -__expf(v.y);
        A[q*4+2] = -__expf(v.z); A[q*4+3] = -__expf(v.w);
    }
    float Dd = ds_[(e*KDn+k)*DD + d];
    size_t base = (size_t)((e*BB+b)*KDn + k)*LL*DD;
    size_t bbc  = (size_t)((e*BB+b)*KDn + k)*LL*NS;
    float h[NS];
    #pragma unroll
    for (int n = 0; n < NS; n++) h[n] = 0.f;
    __shared__ float sB[NS], sC[NS];
    for (int l = 0; l < LL; l++){
        if (d < NS)            sB[d]      = g_Bm[bbc + l*NS + d];
        else if (d < 2*NS)     sC[d-NS]   = g_Cm[bbc + l*NS + (d-NS)];
        __syncthreads();
        float dt = g_dt[base + l*DD + d];
        float xv = g_xs[base + l*DD + d];
        float dx = dt*xv;
        float y = 0.f;
        #pragma unroll
        for (int n = 0; n < NS; n++){
            h[n] = h[n]*__expf(dt*A[n]) + dx*sB[n];
            y += h[n]*sC[n];
        }
        g_ys[base + l*DD + d] = y + Dd*xv;
        __syncthreads();
    }
}

// ---------------- block reduction (sum, sumsq) over 512 threads ------------
__device__ __forceinline__ float2 blockReduce2(float a, float b){
    __shared__ float sa[16], sb[16];
    __shared__ float2 res;
    int lane = threadIdx.x & 31, w = threadIdx.x >> 5;
    #pragma unroll
    for (int o = 16; o; o >>= 1){
        a += __shfl_xor_sync(0xffffffffu, a, o);
        b += __shfl_xor_sync(0xffffffffu, b, o);
    }
    __syncthreads();           // guard against previous call's readers
    if (lane == 0){ sa[w] = a; sb[w] = b; }
    __syncthreads();
    if (w == 0){
        a = (lane < 16) ? sa[lane] : 0.f;
        b = (lane < 16) ? sb[lane] : 0.f;
        #pragma unroll
        for (int o = 8; o; o >>= 1){
            a += __shfl_xor_sync(0xffffffffu, a, o);
            b += __shfl_xor_sync(0xffffffffu, b, o);
        }
        if (lane == 0){ res.x = a; res.y = b; }
    }
    __syncthreads();
    return res;
}

// ---------------- K7: combine directions + LN + silu(z) gate + pool + LN ---
__global__ void k_combine(const float* __restrict__ og_, const float* __restrict__ ob_,
                          const float* __restrict__ ng_, const float* __restrict__ nb_){
    int b = blockIdx.x, e = blockIdx.y, d = threadIdx.x;   // 512 threads
    size_t yb = (size_t)(e*BB+b)*KDn*LL*DD;
    const float* zrow = g_xz + (size_t)(e*BB+b)*LL*C2 + DD;  // z channels
    float og = og_[e*DD+d], ob = ob_[e*DD+d];
    float pooled = 0.f;
    for (int l = 0; l < LL; l++){
        int i = l/7, j = l - 7*i;
        int lv = j*7 + i;
        float v = g_ys[yb + (0*LL + l       )*DD + d]
                + g_ys[yb + (1*LL + (48-l)  )*DD + d]
                + g_ys[yb + (2*LL + lv      )*DD + d]
                + g_ys[yb + (3*LL + (48-lv) )*DD + d];
        float2 ss = blockReduce2(v, v*v);
        float mu = ss.x*(1.f/512.f);
        float var = ss.y*(1.f/512.f) - mu*mu;
        float rs = rsqrtf(var + 1e-5f);
        float yn = (v - mu)*rs*og + ob;
        float z = zrow[l*C2 + d];
        pooled += yn * (z / (1.f + __expf(-z)));
    }
    pooled *= (1.f/49.f);
    float2 ss = blockReduce2(pooled, pooled*pooled);
    float mu = ss.x*(1.f/512.f);
    float var = ss.y*(1.f/512.f) - mu*mu;
    float rs = rsqrtf(var + 1e-5f);
    g_allout[(e*BB+b)*DD + d] = (pooled - mu)*rs*ng_[e*DD+d] + nb_[e*DD+d];
}

// ---------------- K8: mixture + aux loss output -----------------------------
__global__ void k_mix(float* __restrict__ out, int out_size){
    int b = blockIdx.x, d = threadIdx.x;
    int   a0 = g_topi[b*2], a1 = g_topi[b*2+1];
    float v0 = g_topv[b*2], v1 = g_topv[b*2+1];
    out[b*DD + d] = v0*g_allout[(a0*BB+b)*DD + d] + v1*g_allout[(a1*BB+b)*DD + d];
    if (b == 0 && d == 0 && out_size > BB*DD) out[BB*DD] = g_aux;
}

// ---------------- launch ----------------------------------------------------
extern "C" void kernel_launch(void* const* d_in, const int* in_sizes, int n_in,
                              void* d_out, int out_size){
    const float* x    = (const float*)d_in[0];
    const float* wg   = (const float*)d_in[1];
    const float* bg   = (const float*)d_in[2];
    const float* ipw  = (const float*)d_in[3];
    const float* ipb  = (const float*)d_in[4];
    const float* cw   = (const float*)d_in[5];
    const float* cb   = (const float*)d_in[6];
    const float* xpw  = (const float*)d_in[7];
    const float* dtw  = (const float*)d_in[8];
    const float* dtb  = (const float*)d_in[9];
    const float* alog = (const float*)d_in[10];
    const float* ds   = (const float*)d_in[11];
    const float* ong  = (const float*)d_in[12];
    const float* onb  = (const float*)d_in[13];
    const float* ng   = (const float*)d_in[14];
    const float* nb   = (const float*)d_in[15];
    float* out = (float*)d_out;

    const int smem_inproj = 51*DD*sizeof(float);   // 104448 B
    cudaFuncSetAttribute(k_inproj, cudaFuncAttributeMaxDynamicSharedMemorySize, smem_inproj);
    cudaFuncSetAttribute(k_xdbl, cudaFuncAttributeMaxDynamicSharedMemorySize, XD_SMEM_BYTES);

    k_gate   <<<32, 512>>>(x, wg, bg);
    k_gatefin<<<1, 32>>>();
    k_inproj <<<dim3(32,4), 256, smem_inproj>>>(x, ipw, ipb);
    k_conv   <<<dim3(32,4,2), 256>>>(cw, cb);
    k_xdbl   <<<512, 512, XD_SMEM_BYTES>>>(xpw, dtw, dtb);
    k_scan   <<<512, 512>>>(alog, ds);
    k_combine<<<dim3(32,4), 512>>>(ong, onb, ng, nb);
    k_mix    <<<32, 512>>>(out, out_size);
}

// round 3
// speedup vs baseline: 9.3429x; 1.4545x over previous
#include <cuda_runtime.h>
#include <math.h>

// Problem constants
#define EE  4      // experts
#define BB  32     // batch
#define HH  7
#define LL  49     // H*W
#define DD  512    // dim
#define C2  1024   // 2*dim
#define RR  32     // DT_RANK
#define NS  16     // N_STATE
#define KDn 4      // directions

// ---------------- scratch (device globals; no allocation allowed) ----------
__device__ float g_z [EE*BB*LL*DD];          // z half of in_proj [e][b][l][d]
__device__ float g_xs[EE*BB*KDn*LL*DD];      // 4-direction scan inputs [e][b][k][l][d]
__device__ float g_ys[EE*BB*KDn*LL*DD];      // scan outputs [e][b][k][l][d]
__device__ float g_raw[BB*EE];
__device__ float g_aux;
__device__ int   g_topi[BB*2];
__device__ float g_topv[BB*2];
__device__ float g_allout[EE*BB*DD];

// ---------------- f32x2 packed FMA helpers (sm_103a) -----------------------
__device__ __forceinline__ unsigned long long pk2(float lo, float hi){
    unsigned long long r;
    asm("mov.b64 %0, {%1, %2};" : "=l"(r) : "f"(lo), "f"(hi));
    return r;
}
__device__ __forceinline__ void fma2(unsigned long long& d, unsigned long long a, unsigned long long b){
    asm("fma.rn.f32x2 %0, %1, %2, %0;" : "+l"(d) : "l"(a), "l"(b));
}
__device__ __forceinline__ void upk2(unsigned long long v, float& lo, float& hi){
    asm("mov.b64 {%0, %1}, %2;" : "=f"(lo), "=f"(hi) : "l"(v));
}

// ---------------- K1: gate logits + softmax per batch ----------------------
__global__ void k_gate(const float* __restrict__ x, const float* __restrict__ wg,
                       const float* __restrict__ bg){
    int b = blockIdx.x, tid = threadIdx.x;           // 512 threads, tid = channel
    const float* xb = x + (size_t)b*LL*DD + tid;
    float s = 0.f;
    #pragma unroll 7
    for (int l = 0; l < LL; l++) s += xb[l*DD];
    s *= (1.f/49.f);
    float p0 = s*wg[tid*EE+0], p1 = s*wg[tid*EE+1];
    float p2 = s*wg[tid*EE+2], p3 = s*wg[tid*EE+3];
    #pragma unroll
    for (int o = 16; o; o >>= 1){
        p0 += __shfl_xor_sync(0xffffffffu, p0, o);
        p1 += __shfl_xor_sync(0xffffffffu, p1, o);
        p2 += __shfl_xor_sync(0xffffffffu, p2, o);
        p3 += __shfl_xor_sync(0xffffffffu, p3, o);
    }
    __shared__ float sp[16][4];
    int w = tid >> 5, lane = tid & 31;
    if (lane == 0){ sp[w][0]=p0; sp[w][1]=p1; sp[w][2]=p2; sp[w][3]=p3; }
    __syncthreads();
    if (tid == 0){
        float lg[4];
        for (int e = 0; e < 4; e++){
            float a = bg[e];
            for (int ww = 0; ww < 16; ww++) a += sp[ww][e];
            lg[e] = a;
        }
        float m = fmaxf(fmaxf(lg[0],lg[1]), fmaxf(lg[2],lg[3]));
        float ex[4], se = 0.f;
        for (int e = 0; e < 4; e++){ ex[e] = expf(lg[e]-m); se += ex[e]; }
        for (int e = 0; e < 4; e++) g_raw[b*4+e] = ex[e]/se;
    }
}

// ---------------- K2: top-k, mask, denom, aux loss, gate scores ------------
__global__ void k_gatefin(){
    __shared__ float sraw[32][4];
    __shared__ float smask[32][4];
    __shared__ float sden[4];
    int b = threadIdx.x;  // 32 threads
    float r[4];
    #pragma unroll
    for (int e = 0; e < 4; e++){ r[e] = g_raw[b*4+e]; sraw[b][e] = r[e]; }
    int i0 = 0; float m0 = r[0];
    #pragma unroll
    for (int e = 1; e < 4; e++) if (r[e] > m0){ m0 = r[e]; i0 = e; }
    int i1 = -1; float m1 = -1e30f;
    #pragma unroll
    for (int e = 0; e < 4; e++) if (e != i0 && r[e] > m1){ m1 = r[e]; i1 = e; }
    #pragma unroll
    for (int e = 0; e < 4; e++) smask[b][e] = (e==i0 || e==i1) ? 1.f : 0.f;
    __syncthreads();
    if (b == 0){
        float aux = 0.f;
        for (int e = 0; e < 4; e++){
            float ds = 0.f, imp = 0.f, ld = 0.f;
            for (int bb = 0; bb < 32; bb++){
                ds  += sraw[bb][e]*smask[bb][e];
                imp += sraw[bb][e];
                ld  += smask[bb][e];
            }
            sden[e] = ds + 1e-6f;
            imp *= (1.f/32.f); ld *= (1.f/32.f);
            aux += (ld-imp)*(ld-imp);
        }
        g_aux = 0.01f * aux * 0.25f;
    }
    __syncthreads();
    const float cap = 40.f;   // int(1.25*32)
    float s0 = r[i0]*cap/sden[i0];
    float s1 = r[i1]*cap/sden[i1];
    int a0 = i0, a1 = i1; float v0 = s0, v1 = s1;
    if (v1 > v0 || (v1 == v0 && a1 < a0)){
        int t = a0; a0 = a1; a1 = t;
        float tv = v0; v0 = v1; v1 = tv;
    }
    g_topi[b*2] = a0; g_topi[b*2+1] = a1;
    g_topv[b*2] = v0; g_topv[b*2+1] = v1;
}

// ---------------- K3: in_proj GEMM + fused depthwise conv + scatter --------
// Block = (b,e), 256 threads. GEMM 49x512 @ 512x1024; xin half -> smem,
// z half -> g_z; then depthwise 3x3 conv + silu + 4-direction scatter to g_xs.
#define IP_SMEM ((51*DD + LL*DD)*4)   // 104448 + 100352 = 204800
__global__ void __launch_bounds__(256, 1)
k_inproj(const float* __restrict__ x, const float* __restrict__ Wi,
         const float* __restrict__ bi, const float* __restrict__ cw,
         const float* __restrict__ cb){
    extern __shared__ float sxh[];     // [0, 51*512): x rows (49,50 zero pad)
    float* sxin = sxh + 51*DD;         // [51*512, +49*512): conv input staging
    int b = blockIdx.x, e = blockIdx.y, tid = threadIdx.x;
    const float* xb = x + (size_t)b*LL*DD;
    for (int i = tid; i < LL*DD; i += 256) sxh[i] = xb[i];
    for (int i = LL*DD + tid; i < 51*DD; i += 256) sxh[i] = 0.f;
    __syncthreads();
    const float* We = Wi + (size_t)e*DD*C2;
    int c0 = tid*4;
    bool is_xin = (c0 < DD);
    float* zout = g_z + (size_t)(e*BB+b)*LL*DD;
    float4 bia = *(const float4*)(bi + e*C2 + c0);
    for (int lt = 0; lt < 3; lt++){
        int base = lt*17;
        unsigned long long acc[34];
        #pragma unroll
        for (int i = 0; i < 34; i++) acc[i] = 0ull;
        #pragma unroll 2
        for (int kk = 0; kk < DD; kk++){
            float4 w = *(const float4*)(We + (size_t)kk*C2 + c0);
            unsigned long long wa = pk2(w.x, w.y);
            unsigned long long wb = pk2(w.z, w.w);
            const float* xr = sxh + base*DD + kk;
            #pragma unroll
            for (int i = 0; i < 17; i++){
                float xk = xr[i*DD];
                unsigned long long xp = pk2(xk, xk);
                fma2(acc[2*i],   wa, xp);
                fma2(acc[2*i+1], wb, xp);
            }
        }
        #pragma unroll
        for (int i = 0; i < 17; i++){
            int l = base + i;
            if (l < LL){
                float r0,r1,r2,r3;
                upk2(acc[2*i],   r0, r1);
                upk2(acc[2*i+1], r2, r3);
                r0 += bia.x; r1 += bia.y; r2 += bia.z; r3 += bia.w;
                if (is_xin){
                    *(float4*)(sxin + (size_t)l*DD + c0) = make_float4(r0,r1,r2,r3);
                } else {
                    *(float4*)(zout + (size_t)l*DD + (c0 - DD)) = make_float4(r0,r1,r2,r3);
                }
            }
        }
    }
    __syncthreads();
    // ---- depthwise 3x3 conv + silu + scatter; thread handles d = tid, tid+256
    float* xsb = g_xs + (size_t)(e*BB+b)*KDn*LL*DD;
    #pragma unroll
    for (int half = 0; half < 2; half++){
        int d = tid + half*256;
        float w9[9];
        #pragma unroll
        for (int t = 0; t < 9; t++) w9[t] = cw[(e*DD+d)*9 + t];
        float bias = cb[e*DD+d];
        float row[3][7];   // rolling rows: row[(i)%3]
        // preload rows 0 and 1
        #pragma unroll
        for (int j = 0; j < 7; j++){
            row[0][j] = sxin[(0*7+j)*DD + d];
            row[1][j] = sxin[(1*7+j)*DD + d];
        }
        #pragma unroll
        for (int i = 0; i < 7; i++){
            // row i+1 already loaded in row[(i+1)%3]; load row i+1's successor
            if (i < 6){
                #pragma unroll
                for (int j = 0; j < 7; j++)
                    row[(i+1)%3][j] = sxin[((i+1)*7+j)*DD + d];
            }
            const float* rm = (i > 0) ? row[(i-1)%3] : nullptr;
            const float* rc = row[i%3];
            const float* rp = (i < 6) ? row[(i+1)%3] : nullptr;
            #pragma unroll
            for (int j = 0; j < 7; j++){
                float a = bias;
                #pragma unroll
                for (int dj = 0; dj < 3; dj++){
                    int jj = j + dj - 1;
                    if (jj < 0 || jj > 6) continue;
                    if (i > 0) a += rm[jj]*w9[0*3+dj];
                    a += rc[jj]*w9[1*3+dj];
                    if (i < 6) a += rp[jj]*w9[2*3+dj];
                }
                float v = a / (1.f + __expf(-a));   // silu
                int l  = i*7 + j;
                int lv = j*7 + i;
                xsb[(0*LL + l       )*DD + d] = v;
                xsb[(1*LL + (48-l)  )*DD + d] = v;
                xsb[(2*LL + lv      )*DD + d] = v;
                xsb[(3*LL + (48-lv) )*DD + d] = v;
            }
        }
    }
}
// NOTE: rolling-row indexing above: at iteration i, rows i-1,i,i+1 live in
// row[(i-1)%3], row[i%3], row[(i+1)%3]; preload fills 0,1; body fills i+1.

// ---------------- K5: fused x_dbl + dt_proj + selective scan ---------------
// Block per (e,b,k), 512 threads.
//   Phase A: sx tile (49x512) + xpw (64 rows, pad 514) in smem; x_dbl to regs.
//   Stage:   dt-rank -> sdbl, B/C -> sBC, dtw^T -> dtwT (all alias xpw region).
//   Phase B: per 4-l group compute dt=softplus(...), immediately run scan steps.
#define XDW   514                     // xpw smem row stride (floats)
#define DTW_S 513
#define XD_SMEM_BYTES ((LL*DD + 64*XDW)*4)   // 231936
__global__ void __launch_bounds__(512, 1)
k_xdblscan(const float* __restrict__ xpw_, const float* __restrict__ dtw_,
           const float* __restrict__ dtb_, const float* __restrict__ alog_,
           const float* __restrict__ ds_){
    extern __shared__ float sm[];
    float* sx  = sm;                 // LL*DD floats
    float* wsm = sm + LL*DD;         // 64 x XDW  (phase A)
    float* dtwT = sm + LL*DD;                    // 32 x DTW_S (phase B) aliases wsm
    float* sdbl = dtwT + 32*DTW_S;               // 49 x 32 dt-rank
    float* sBC  = sdbl + LL*32;                  // 49 x 32 (B | C)
    int idx = blockIdx.x;
    int k = idx & 3, b = (idx >> 2) & 31, e = idx >> 7;
    int tid = threadIdx.x;
    int lane = tid & 31, w = tid >> 5;

    const float* xsrow = g_xs + (size_t)((e*BB+b)*KDn + k)*LL*DD;
    const float* xpw = xpw_ + (size_t)((e*KDn+k)*64)*DD;   // [c][d]
    const float* dtw = dtw_ + (size_t)((e*KDn+k)*DD)*RR;   // [d][r]
    const float* dtb = dtb_ + (e*KDn+k)*DD;
    float* ysout = g_ys + (size_t)((e*BB+b)*KDn + k)*LL*DD;

    // load sx tile + xpw (coalesced)
    for (int i = tid; i < LL*DD; i += 512) sx[i] = xsrow[i];
    for (int i = tid; i < 64*DD; i += 512){
        int c = i >> 9, dd = i & 511;
        wsm[c*XDW + dd] = xpw[i];
    }
    __syncthreads();

    // ---- Phase A: x_dbl[c][l] = sum_d sx[l][d]*w[c][d] ----
    int c0 = lane, c1 = lane + 32;
    float acc0[3] = {0.f,0.f,0.f};
    float acc1[3] = {0.f,0.f,0.f};
    const float* w0p = wsm + c0*XDW;
    const float* w1p = wsm + c1*XDW;
    {
        const float* x0 = sx + (w      )*DD;
        const float* x1 = sx + (w + 16 )*DD;
        const float* x2 = sx + (w + 32 )*DD;
        #pragma unroll 4
        for (int kk = 0; kk < DD; kk += 2){
            float2 wa = *(const float2*)(w0p + kk);
            float2 wb = *(const float2*)(w1p + kk);
            float2 xv;
            xv = *(const float2*)(x0 + kk);
            acc0[0] += xv.x*wa.x + xv.y*wa.y;  acc1[0] += xv.x*wb.x + xv.y*wb.y;
            xv = *(const float2*)(x1 + kk);
            acc0[1] += xv.x*wa.x + xv.y*wa.y;  acc1[1] += xv.x*wb.x + xv.y*wb.y;
            xv = *(const float2*)(x2 + kk);
            acc0[2] += xv.x*wa.x + xv.y*wa.y;  acc1[2] += xv.x*wb.x + xv.y*wb.y;
        }
    }
    float t0 = 0.f, t1 = 0.f;
    if (w == 0){
        const float* x3 = sx + 48*DD;
        #pragma unroll 4
        for (int kk = 0; kk < DD; kk += 2){
            float2 wa = *(const float2*)(w0p + kk);
            float2 wb = *(const float2*)(w1p + kk);
            float2 xv = *(const float2*)(x3 + kk);
            t0 += xv.x*wa.x + xv.y*wa.y;
            t1 += xv.x*wb.x + xv.y*wb.y;
        }
    }
    __syncthreads();   // all wsm reads done; region reusable

    // stage dt-rank + B/C into smem; load dtw transposed
    #pragma unroll
    for (int i = 0; i < 3; i++){
        int l = w + 16*i;
        sdbl[l*32 + lane] = acc0[i];
        sBC [l*32 + lane] = acc1[i];   // lane<16: B[n], lane>=16: C[n-16]
    }
    if (w == 0){
        sdbl[48*32 + lane] = t0;
        sBC [48*32 + lane] = t1;
    }
    for (int i = tid; i < DD*RR; i += 512){
        int dd = i >> 5, r = i & 31;
        dtwT[r*DTW_S + dd] = dtw[i];
    }
    __syncthreads();

    // ---- Phase B + scan, thread dd = tid owns channel dd ----
    int dd = tid;
    float bias = dtb[dd];
    float A[NS];
    {
        const float4* al = (const float4*)(alog_ + ((size_t)((e*KDn+k)*DD) + dd)*NS);
        #pragma unroll
        for (int q = 0; q < 4; q++){
            float4 v = al[q];
            A[q*4+0] = -__expf(v.x); A[q*4+1] = -__expf(v.y);
            A[q*4+2] = -__expf(v.z); A[q*4+3] = -__expf(v.w);
        }
    }
    float Dd = ds_[(e*KDn+k)*DD + dd];
    float h[NS];
    #pragma unroll
    for (int n = 0; n < NS; n++) h[n] = 0.f;

    #pragma unroll 1
    for (int lg = 0; lg < 13; lg++){
        int l0 = lg*4;
        int nl = (lg < 12) ? 4 : 1;
        float a0 = bias, a1 = bias, a2 = bias, a3 = bias;
        const float* s0 = sdbl + (l0    )*32;
        const float* s1 = sdbl + (l0 + 1)*32;
        const float* s2 = sdbl + (l0 + 2)*32;
        const float* s3 = sdbl + (l0 + 3)*32;
        if (nl == 4){
            #pragma unroll
            for (int r = 0; r < RR; r++){
                float wv = dtwT[r*DTW_S + dd];
                a0 += s0[r]*wv; a1 += s1[r]*wv; a2 += s2[r]*wv; a3 += s3[r]*wv;
            }
        } else {
            #pragma unroll
            for (int r = 0; r < RR; r++){
                float wv = dtwT[r*DTW_S + dd];
                a0 += s0[r]*wv;
            }
        }
        float dts[4] = {a0, a1, a2, a3};
        #pragma unroll
        for (int j = 0; j < 4; j++){
            if (j >= nl) break;
            int l = l0 + j;
            float a = dts[j];
            float dtv = fmaxf(a, 0.f) + log1pf(__expf(-fabsf(a)));
            float xv = sx[l*DD + dd];
            float dx = dtv*xv;
            const float* bc = sBC + l*32;
            float y = 0.f;
            #pragma unroll
            for (int n = 0; n < NS; n++){
                h[n] = h[n]*__expf(dtv*A[n]) + dx*bc[n];
                y += h[n]*bc[16+n];
            }
            ysout[l*DD + dd] = y + Dd*xv;
        }
    }
}

// ---------------- block reduction (sum, sumsq) over 512 threads ------------
__device__ __forceinline__ float2 blockReduce2(float a, float b){
    __shared__ float sa[16], sb[16];
    __shared__ float2 res;
    int lane = threadIdx.x & 31, w = threadIdx.x >> 5;
    #pragma unroll
    for (int o = 16; o; o >>= 1){
        a += __shfl_xor_sync(0xffffffffu, a, o);
        b += __shfl_xor_sync(0xffffffffu, b, o);
    }
    __syncthreads();
    if (lane == 0){ sa[w] = a; sb[w] = b; }
    __syncthreads();
    if (w == 0){
        a = (lane < 16) ? sa[lane] : 0.f;
        b = (lane < 16) ? sb[lane] : 0.f;
        #pragma unroll
        for (int o = 8; o; o >>= 1){
            a += __shfl_xor_sync(0xffffffffu, a, o);
            b += __shfl_xor_sync(0xffffffffu, b, o);
        }
        if (lane == 0){ res.x = a; res.y = b; }
    }
    __syncthreads();
    return res;
}

// ---------------- K7: combine directions + LN + silu(z) gate + pool + LN ---
#define CB_SMEM ((LL*DD + 128)*4)
__global__ void __launch_bounds__(512, 1)
k_combine(const float* __restrict__ og_, const float* __restrict__ ob_,
          const float* __restrict__ ng_, const float* __restrict__ nb_){
    extern __shared__ float sv[];        // 49*512 + mu/rs
    float* smu = sv + LL*DD;             // 49
    float* srs = smu + 56;               // 49
    int b = blockIdx.x, e = blockIdx.y, d = threadIdx.x;   // 512 threads
    size_t yb = (size_t)(e*BB+b)*KDn*LL*DD;
    // batch-load all 4 directions, combine into sv[l][d]
    #pragma unroll 1
    for (int l = 0; l < LL; l++){
        int i = l/7, j = l - 7*i;
        int lv = j*7 + i;
        float v = g_ys[yb + (0*LL + l       )*DD + d]
                + g_ys[yb + (1*LL + (48-l)  )*DD + d]
                + g_ys[yb + (2*LL + lv      )*DD + d]
                + g_ys[yb + (3*LL + (48-lv) )*DD + d];
        sv[l*DD + d] = v;
    }
    __syncthreads();
    // warp-per-row layernorm stats
    int w = d >> 5, lane = d & 31;
    for (int l = w; l < LL; l += 16){
        float a = 0.f, s2 = 0.f;
        #pragma unroll
        for (int jj = 0; jj < 16; jj++){
            float xv = sv[l*DD + lane + 32*jj];
            a += xv; s2 += xv*xv;
        }
        #pragma unroll
        for (int o = 16; o; o >>= 1){
            a  += __shfl_xor_sync(0xffffffffu, a, o);
            s2 += __shfl_xor_sync(0xffffffffu, s2, o);
        }
        if (lane == 0){
            float mu = a*(1.f/512.f);
            float var = s2*(1.f/512.f) - mu*mu;
            smu[l] = mu;
            srs[l] = rsqrtf(var + 1e-5f);
        }
    }
    __syncthreads();
    float og = og_[e*DD+d], ob = ob_[e*DD+d];
    const float* zrow = g_z + (size_t)(e*BB+b)*LL*DD + d;
    float pooled = 0.f;
    #pragma unroll 7
    for (int l = 0; l < LL; l++){
        float v = sv[l*DD + d];
        float yn = (v - smu[l])*srs[l]*og + ob;
        float z = zrow[l*DD];
        pooled += yn * (z / (1.f + __expf(-z)));
    }
    pooled *= (1.f/49.f);
    float2 ss = blockReduce2(pooled, pooled*pooled);
    float mu = ss.x*(1.f/512.f);
    float var = ss.y*(1.f/512.f) - mu*mu;
    float rs = rsqrtf(var + 1e-5f);
    g_allout[(e*BB+b)*DD + d] = (pooled - mu)*rs*ng_[e*DD+d] + nb_[e*DD+d];
}

// ---------------- K8: mixture + aux loss output -----------------------------
__global__ void k_mix(float* __restrict__ out, int out_size){
    int b = blockIdx.x, d = threadIdx.x;
    int   a0 = g_topi[b*2], a1 = g_topi[b*2+1];
    float v0 = g_topv[b*2], v1 = g_topv[b*2+1];
    out[b*DD + d] = v0*g_allout[(a0*BB+b)*DD + d] + v1*g_allout[(a1*BB+b)*DD + d];
    if (b == 0 && d == 0 && out_size > BB*DD) out[BB*DD] = g_aux;
}

// ---------------- launch ----------------------------------------------------
extern "C" void kernel_launch(void* const* d_in, const int* in_sizes, int n_in,
                              void* d_out, int out_size){
    const float* x    = (const float*)d_in[0];
    const float* wg   = (const float*)d_in[1];
    const float* bg   = (const float*)d_in[2];
    const float* ipw  = (const float*)d_in[3];
    const float* ipb  = (const float*)d_in[4];
    const float* cw   = (const float*)d_in[5];
    const float* cb   = (const float*)d_in[6];
    const float* xpw  = (const float*)d_in[7];
    const float* dtw  = (const float*)d_in[8];
    const float* dtb  = (const float*)d_in[9];
    const float* alog = (const float*)d_in[10];
    const float* ds   = (const float*)d_in[11];
    const float* ong  = (const float*)d_in[12];
    const float* onb  = (const float*)d_in[13];
    const float* ng   = (const float*)d_in[14];
    const float* nb   = (const float*)d_in[15];
    float* out = (float*)d_out;

    cudaFuncSetAttribute(k_inproj,   cudaFuncAttributeMaxDynamicSharedMemorySize, IP_SMEM);
    cudaFuncSetAttribute(k_xdblscan, cudaFuncAttributeMaxDynamicSharedMemorySize, XD_SMEM_BYTES);
    cudaFuncSetAttribute(k_combine,  cudaFuncAttributeMaxDynamicSharedMemorySize, CB_SMEM);

    k_gate    <<<32, 512>>>(x, wg, bg);
    k_gatefin <<<1, 32>>>();
    k_inproj  <<<dim3(32,4), 256, IP_SMEM>>>(x, ipw, ipb, cw, cb);
    k_xdblscan<<<512, 512, XD_SMEM_BYTES>>>(xpw, dtw, dtb, alog, ds);
    k_combine <<<dim3(32,4), 512, CB_SMEM>>>(ong, onb, ng, nb);
    k_mix     <<<32, 512>>>(out, out_size);
}

// round 4
// speedup vs baseline: 9.7658x; 1.0453x over previous
#include <cuda_runtime.h>
#include <math.h>

// Problem constants
#define EE  4      // experts
#define BB  32     // batch
#define HH  7
#define LL  49     // H*W
#define DD  512    // dim
#define C2  1024   // 2*dim
#define RR  32     // DT_RANK
#define NS  16     // N_STATE
#define KDn 4      // directions

// ---------------- scratch (device globals; no allocation allowed) ----------
__device__ float g_z [EE*BB*LL*DD];          // z half of in_proj [e][b][l][d]
__device__ float g_xs[EE*BB*KDn*LL*DD];      // 4-direction scan inputs [e][b][k][l][d]
__device__ float g_ys[EE*BB*KDn*LL*DD];      // scan outputs [e][b][k][l][d]
__device__ float g_raw[BB*EE];
__device__ float g_aux;
__device__ int   g_topi[BB*2];
__device__ float g_topv[BB*2];
__device__ float g_allout[EE*BB*DD];

// ---------------- f32x2 packed FMA helpers (sm_103a) -----------------------
__device__ __forceinline__ unsigned long long pk2(float lo, float hi){
    unsigned long long r;
    asm("mov.b64 %0, {%1, %2};" : "=l"(r) : "f"(lo), "f"(hi));
    return r;
}
__device__ __forceinline__ void fma2(unsigned long long& d, unsigned long long a, unsigned long long b){
    asm("fma.rn.f32x2 %0, %1, %2, %0;" : "+l"(d) : "l"(a), "l"(b));
}
__device__ __forceinline__ void upk2(unsigned long long v, float& lo, float& hi){
    asm("mov.b64 {%0, %1}, %2;" : "=f"(lo), "=f"(hi) : "l"(v));
}
__device__ __forceinline__ float ex2f(float x){
    float r; asm("ex2.approx.f32 %0, %1;" : "=f"(r) : "f"(x)); return r;
}

// ---------------- K1: gate logits + softmax per batch ----------------------
__global__ void k_gate(const float* __restrict__ x, const float* __restrict__ wg,
                       const float* __restrict__ bg){
    int b = blockIdx.x, tid = threadIdx.x;           // 512 threads, tid = channel
    const float* xb = x + (size_t)b*LL*DD + tid;
    float s = 0.f;
    #pragma unroll 7
    for (int l = 0; l < LL; l++) s += xb[l*DD];
    s *= (1.f/49.f);
    float p0 = s*wg[tid*EE+0], p1 = s*wg[tid*EE+1];
    float p2 = s*wg[tid*EE+2], p3 = s*wg[tid*EE+3];
    #pragma unroll
    for (int o = 16; o; o >>= 1){
        p0 += __shfl_xor_sync(0xffffffffu, p0, o);
        p1 += __shfl_xor_sync(0xffffffffu, p1, o);
        p2 += __shfl_xor_sync(0xffffffffu, p2, o);
        p3 += __shfl_xor_sync(0xffffffffu, p3, o);
    }
    __shared__ float sp[16][4];
    int w = tid >> 5, lane = tid & 31;
    if (lane == 0){ sp[w][0]=p0; sp[w][1]=p1; sp[w][2]=p2; sp[w][3]=p3; }
    __syncthreads();
    if (tid == 0){
        float lg[4];
        for (int e = 0; e < 4; e++){
            float a = bg[e];
            for (int ww = 0; ww < 16; ww++) a += sp[ww][e];
            lg[e] = a;
        }
        float m = fmaxf(fmaxf(lg[0],lg[1]), fmaxf(lg[2],lg[3]));
        float ex[4], se = 0.f;
        for (int e = 0; e < 4; e++){ ex[e] = expf(lg[e]-m); se += ex[e]; }
        for (int e = 0; e < 4; e++) g_raw[b*4+e] = ex[e]/se;
    }
}

// ---------------- K2: top-k, mask, denom, aux loss, gate scores ------------
__global__ void k_gatefin(){
    __shared__ float sraw[32][4];
    __shared__ float smask[32][4];
    __shared__ float sden[4];
    int b = threadIdx.x;  // 32 threads
    float r[4];
    #pragma unroll
    for (int e = 0; e < 4; e++){ r[e] = g_raw[b*4+e]; sraw[b][e] = r[e]; }
    int i0 = 0; float m0 = r[0];
    #pragma unroll
    for (int e = 1; e < 4; e++) if (r[e] > m0){ m0 = r[e]; i0 = e; }
    int i1 = -1; float m1 = -1e30f;
    #pragma unroll
    for (int e = 0; e < 4; e++) if (e != i0 && r[e] > m1){ m1 = r[e]; i1 = e; }
    #pragma unroll
    for (int e = 0; e < 4; e++) smask[b][e] = (e==i0 || e==i1) ? 1.f : 0.f;
    __syncthreads();
    if (b == 0){
        float aux = 0.f;
        for (int e = 0; e < 4; e++){
            float ds = 0.f, imp = 0.f, ld = 0.f;
            for (int bb = 0; bb < 32; bb++){
                ds  += sraw[bb][e]*smask[bb][e];
                imp += sraw[bb][e];
                ld  += smask[bb][e];
            }
            sden[e] = ds + 1e-6f;
            imp *= (1.f/32.f); ld *= (1.f/32.f);
            aux += (ld-imp)*(ld-imp);
        }
        g_aux = 0.01f * aux * 0.25f;
    }
    __syncthreads();
    const float cap = 40.f;   // int(1.25*32)
    float s0 = r[i0]*cap/sden[i0];
    float s1 = r[i1]*cap/sden[i1];
    int a0 = i0, a1 = i1; float v0 = s0, v1 = s1;
    if (v1 > v0 || (v1 == v0 && a1 < a0)){
        int t = a0; a0 = a1; a1 = t;
        float tv = v0; v0 = v1; v1 = tv;
    }
    g_topi[b*2] = a0; g_topi[b*2+1] = a1;
    g_topv[b*2] = v0; g_topv[b*2+1] = v1;
}

// ---------------- K3: in_proj GEMM + fused depthwise conv + scatter --------
#define IP_SMEM ((51*DD + LL*DD)*4)   // 104448 + 100352 = 204800
__global__ void __launch_bounds__(256, 1)
k_inproj(const float* __restrict__ x, const float* __restrict__ Wi,
         const float* __restrict__ bi, const float* __restrict__ cw,
         const float* __restrict__ cb){
    extern __shared__ float sxh[];     // [0, 51*512): x rows (49,50 zero pad)
    float* sxin = sxh + 51*DD;         // [51*512, +49*512): conv input staging
    int b = blockIdx.x, e = blockIdx.y, tid = threadIdx.x;
    const float* xb = x + (size_t)b*LL*DD;
    for (int i = tid; i < LL*DD; i += 256) sxh[i] = xb[i];
    for (int i = LL*DD + tid; i < 51*DD; i += 256) sxh[i] = 0.f;
    __syncthreads();
    const float* We = Wi + (size_t)e*DD*C2;
    int c0 = tid*4;
    bool is_xin = (c0 < DD);
    float* zout = g_z + (size_t)(e*BB+b)*LL*DD;
    float4 bia = *(const float4*)(bi + e*C2 + c0);
    for (int lt = 0; lt < 3; lt++){
        int base = lt*17;
        unsigned long long acc[34];
        #pragma unroll
        for (int i = 0; i < 34; i++) acc[i] = 0ull;
        #pragma unroll 2
        for (int kk = 0; kk < DD; kk++){
            float4 w = *(const float4*)(We + (size_t)kk*C2 + c0);
            unsigned long long wa = pk2(w.x, w.y);
            unsigned long long wb = pk2(w.z, w.w);
            const float* xr = sxh + base*DD + kk;
            #pragma unroll
            for (int i = 0; i < 17; i++){
                float xk = xr[i*DD];
                unsigned long long xp = pk2(xk, xk);
                fma2(acc[2*i],   wa, xp);
                fma2(acc[2*i+1], wb, xp);
            }
        }
        #pragma unroll
        for (int i = 0; i < 17; i++){
            int l = base + i;
            if (l < LL){
                float r0,r1,r2,r3;
                upk2(acc[2*i],   r0, r1);
                upk2(acc[2*i+1], r2, r3);
                r0 += bia.x; r1 += bia.y; r2 += bia.z; r3 += bia.w;
                if (is_xin){
                    *(float4*)(sxin + (size_t)l*DD + c0) = make_float4(r0,r1,r2,r3);
                } else {
                    *(float4*)(zout + (size_t)l*DD + (c0 - DD)) = make_float4(r0,r1,r2,r3);
                }
            }
        }
    }
    __syncthreads();
    // ---- depthwise 3x3 conv + silu + scatter; thread handles d = tid, tid+256
    float* xsb = g_xs + (size_t)(e*BB+b)*KDn*LL*DD;
    #pragma unroll
    for (int half = 0; half < 2; half++){
        int d = tid + half*256;
        float w9[9];
        #pragma unroll
        for (int t = 0; t < 9; t++) w9[t] = cw[(e*DD+d)*9 + t];
        float bias = cb[e*DD+d];
        float row[3][7];
        #pragma unroll
        for (int j = 0; j < 7; j++){
            row[0][j] = sxin[(0*7+j)*DD + d];
            row[1][j] = sxin[(1*7+j)*DD + d];
        }
        #pragma unroll
        for (int i = 0; i < 7; i++){
            if (i < 6){
                #pragma unroll
                for (int j = 0; j < 7; j++)
                    row[(i+1)%3][j] = sxin[((i+1)*7+j)*DD + d];
            }
            const float* rm = (i > 0) ? row[(i-1)%3] : nullptr;
            const float* rc = row[i%3];
            const float* rp = (i < 6) ? row[(i+1)%3] : nullptr;
            #pragma unroll
            for (int j = 0; j < 7; j++){
                float a = bias;
                #pragma unroll
                for (int dj = 0; dj < 3; dj++){
                    int jj = j + dj - 1;
                    if (jj < 0 || jj > 6) continue;
                    if (i > 0) a += rm[jj]*w9[0*3+dj];
                    a += rc[jj]*w9[1*3+dj];
                    if (i < 6) a += rp[jj]*w9[2*3+dj];
                }
                float v = a / (1.f + __expf(-a));   // silu
                int l  = i*7 + j;
                int lv = j*7 + i;
                xsb[(0*LL + l       )*DD + d] = v;
                xsb[(1*LL + (48-l)  )*DD + d] = v;
                xsb[(2*LL + lv      )*DD + d] = v;
                xsb[(3*LL + (48-lv) )*DD + d] = v;
            }
        }
    }
}

// ---------------- K5: fused x_dbl + dt_proj + selective scan ---------------
// Block per (e,b,k), 512 threads.
//   Phase A: split-K GEMM (warps 0-7: K[0,256), 8-15: K[256,512)); float4 loads
//            (weights XOR-swizzled in smem, x broadcast), f32x2 packed FMA.
//            Thread tile: 2 c (lane, lane+32) x 6-7 l (warp-group wg).
//   Stage:   dt-rank -> sdbl, B/C -> sBC (split-K reduced); dtw^T -> dtwT.
//   Phase B: per 4-l group compute dt=softplus(...), run scan steps.
#define DTW_S 513
#define XD_SMEM_BYTES ((LL*DD + 64*DD)*4)   // 100352 + 131072 = 231424
__global__ void __launch_bounds__(512, 1)
k_xdblscan(const float* __restrict__ xpw_, const float* __restrict__ dtw_,
           const float* __restrict__ dtb_, const float* __restrict__ alog_,
           const float* __restrict__ ds_){
    extern __shared__ float sm[];
    float* sx  = sm;                 // LL*DD floats
    float* wsm = sm + LL*DD;         // 64 x 512, XOR-swizzled (phase A)
    float* dtwT = sm + LL*DD;        // 32 x DTW_S (phase B) aliases wsm
    float* sdbl = dtwT + 32*DTW_S;   // 49 x 32 dt-rank
    float* sBC  = sdbl + LL*32;      // 49 x 32 (B | C)
    int idx = blockIdx.x;
    int k = idx & 3, b = (idx >> 2) & 31, e = idx >> 7;
    int tid = threadIdx.x;
    int lane = tid & 31, w = tid >> 5;

    const float* xsrow = g_xs + (size_t)((e*BB+b)*KDn + k)*LL*DD;
    const float* xpw = xpw_ + (size_t)((e*KDn+k)*64)*DD;   // [c][d]
    const float* dtw = dtw_ + (size_t)((e*KDn+k)*DD)*RR;   // [d][r]
    const float* dtb = dtb_ + (e*KDn+k)*DD;
    float* ysout = g_ys + (size_t)((e*BB+b)*KDn + k)*LL*DD;

    // load sx tile (coalesced) + xpw into XOR-swizzled smem
    for (int i = tid; i < LL*DD; i += 512) sx[i] = xsrow[i];
    for (int i = tid; i < 64*DD; i += 512){
        int c = i >> 9, dd = i & 511;
        int g = dd >> 2;
        wsm[c*DD + ((((g ^ (c & 7)) << 2)) | (dd & 3))] = xpw[i];
    }
    __syncthreads();

    // ---- Phase A: x_dbl[c][l] = sum_d sx[l][d]*w[c][d], split-K ----
    int wg = w & 7;            // l-group: wg*6..wg*6+5 (wg==0 also handles l=48)
    int ks = w >> 3;           // K-split half
    int kk0 = ks << 8;
    int l0 = wg*6;
    int nl = (wg == 0) ? 7 : 6;
    int c0 = lane, c1 = lane + 32;
    unsigned long long a0[7], a1[7];
    #pragma unroll
    for (int j = 0; j < 7; j++){ a0[j] = 0ull; a1[j] = 0ull; }
    const float* w0base = wsm + c0*DD;
    const float* w1base = wsm + c1*DD;
    int sw = (lane & 7) << 2;     // xor pattern (same for c0,c1)
    #pragma unroll 4
    for (int t = 0; t < 64; t++){
        int kk = kk0 + t*4;
        float4 w0 = *(const float4*)(w0base + (kk ^ sw));
        float4 w1 = *(const float4*)(w1base + (kk ^ sw));
        unsigned long long w0a = pk2(w0.x, w0.y), w0b = pk2(w0.z, w0.w);
        unsigned long long w1a = pk2(w1.x, w1.y), w1b = pk2(w1.z, w1.w);
        #pragma unroll
        for (int j = 0; j < 7; j++){
            if (j < nl){
                int l = (j == 6) ? 48 : (l0 + j);
                float4 xv = *(const float4*)(sx + l*DD + kk);
                unsigned long long xa = pk2(xv.x, xv.y), xb = pk2(xv.z, xv.w);
                fma2(a0[j], w0a, xa); fma2(a0[j], w0b, xb);
                fma2(a1[j], w1a, xa); fma2(a1[j], w1b, xb);
            }
        }
    }
    __syncthreads();   // all wsm/sx phase-A reads done; wsm region reusable

    // stage: split-K half 0 writes, half 1 adds
    if (ks == 0){
        #pragma unroll
        for (int j = 0; j < 7; j++){
            if (j < nl){
                int l = (j == 6) ? 48 : (l0 + j);
                float lo, hi;
                upk2(a0[j], lo, hi); sdbl[l*32 + lane] = lo + hi;
                upk2(a1[j], lo, hi); sBC [l*32 + lane] = lo + hi;
            }
        }
    }
    __syncthreads();
    if (ks == 1){
        #pragma unroll
        for (int j = 0; j < 7; j++){
            if (j < nl){
                int l = (j == 6) ? 48 : (l0 + j);
                float lo, hi;
                upk2(a0[j], lo, hi); sdbl[l*32 + lane] += lo + hi;
                upk2(a1[j], lo, hi); sBC [l*32 + lane] += lo + hi;
            }
        }
    }
    // load dtw transposed into dtwT (disjoint from sdbl/sBC)
    for (int i = tid; i < DD*RR; i += 512){
        int dd = i >> 5, r = i & 31;
        dtwT[r*DTW_S + dd] = dtw[i];
    }
    __syncthreads();

    // ---- Phase B + scan, thread dd = tid owns channel dd ----
    int dd = tid;
    float bias = dtb[dd];
    float A[NS];
    {
        const float4* al = (const float4*)(alog_ + ((size_t)((e*KDn+k)*DD) + dd)*NS);
        const float L2E = 1.44269504088896f;
        #pragma unroll
        for (int q = 0; q < 4; q++){
            float4 v = al[q];
            A[q*4+0] = -__expf(v.x)*L2E; A[q*4+1] = -__expf(v.y)*L2E;
            A[q*4+2] = -__expf(v.z)*L2E; A[q*4+3] = -__expf(v.w)*L2E;
        }
    }
    float Dd = ds_[(e*KDn+k)*DD + dd];
    float h[NS];
    #pragma unroll
    for (int n = 0; n < NS; n++) h[n] = 0.f;

    #pragma unroll 1
    for (int lg = 0; lg < 13; lg++){
        int l0b = lg*4;
        int nlb = (lg < 12) ? 4 : 1;
        float q0 = bias, q1 = bias, q2 = bias, q3 = bias;
        const float* s0 = sdbl + (l0b    )*32;
        const float* s1 = sdbl + (l0b + 1)*32;
        const float* s2 = sdbl + (l0b + 2)*32;
        const float* s3 = sdbl + (l0b + 3)*32;
        if (nlb == 4){
            #pragma unroll
            for (int r = 0; r < RR; r++){
                float wv = dtwT[r*DTW_S + dd];
                q0 += s0[r]*wv; q1 += s1[r]*wv; q2 += s2[r]*wv; q3 += s3[r]*wv;
            }
        } else {
            #pragma unroll
            for (int r = 0; r < RR; r++){
                float wv = dtwT[r*DTW_S + dd];
                q0 += s0[r]*wv;
            }
        }
        float dts[4] = {q0, q1, q2, q3};
        #pragma unroll
        for (int j = 0; j < 4; j++){
            if (j >= nlb) break;
            int l = l0b + j;
            float a = dts[j];
            float dtv = fmaxf(a, 0.f) + log1pf(__expf(-fabsf(a)));
            float xv = sx[l*DD + dd];
            float dx = dtv*xv;
            const float* bc = sBC + l*32;
            float y = 0.f;
            #pragma unroll
            for (int n = 0; n < NS; n++){
                h[n] = h[n]*ex2f(dtv*A[n]) + dx*bc[n];
                y += h[n]*bc[16+n];
            }
            ysout[l*DD + dd] = y + Dd*xv;
        }
    }
}

// ---------------- block reduction (sum, sumsq) over 512 threads ------------
__device__ __forceinline__ float2 blockReduce2(float a, float b){
    __shared__ float sa[16], sb[16];
    __shared__ float2 res;
    int lane = threadIdx.x & 31, w = threadIdx.x >> 5;
    #pragma unroll
    for (int o = 16; o; o >>= 1){
        a += __shfl_xor_sync(0xffffffffu, a, o);
        b += __shfl_xor_sync(0xffffffffu, b, o);
    }
    __syncthreads();
    if (lane == 0){ sa[w] = a; sb[w] = b; }
    __syncthreads();
    if (w == 0){
        a = (lane < 16) ? sa[lane] : 0.f;
        b = (lane < 16) ? sb[lane] : 0.f;
        #pragma unroll
        for (int o = 8; o; o >>= 1){
            a += __shfl_xor_sync(0xffffffffu, a, o);
            b += __shfl_xor_sync(0xffffffffu, b, o);
        }
        if (lane == 0){ res.x = a; res.y = b; }
    }
    __syncthreads();
    return res;
}

// ---------------- K7: combine directions + LN + silu(z) gate + pool + LN ---
#define CB_SMEM ((LL*DD + 128)*4)
__global__ void __launch_bounds__(512, 1)
k_combine(const float* __restrict__ og_, const float* __restrict__ ob_,
          const float* __restrict__ ng_, const float* __restrict__ nb_){
    extern __shared__ float sv[];        // 49*512 + mu/rs
    float* smu = sv + LL*DD;             // 49
    float* srs = smu + 56;               // 49
    int b = blockIdx.x, e = blockIdx.y, d = threadIdx.x;   // 512 threads
    size_t yb = (size_t)(e*BB+b)*KDn*LL*DD;
    #pragma unroll 1
    for (int l = 0; l < LL; l++){
        int i = l/7, j = l - 7*i;
        int lv = j*7 + i;
        float v = g_ys[yb + (0*LL + l       )*DD + d]
                + g_ys[yb + (1*LL + (48-l)  )*DD + d]
                + g_ys[yb + (2*LL + lv      )*DD + d]
                + g_ys[yb + (3*LL + (48-lv) )*DD + d];
        sv[l*DD + d] = v;
    }
    __syncthreads();
    int w = d >> 5, lane = d & 31;
    for (int l = w; l < LL; l += 16){
        float a = 0.f, s2 = 0.f;
        #pragma unroll
        for (int jj = 0; jj < 16; jj++){
            float xv = sv[l*DD + lane + 32*jj];
            a += xv; s2 += xv*xv;
        }
        #pragma unroll
        for (int o = 16; o; o >>= 1){
            a  += __shfl_xor_sync(0xffffffffu, a, o);
            s2 += __shfl_xor_sync(0xffffffffu, s2, o);
        }
        if (lane == 0){
            float mu = a*(1.f/512.f);
            float var = s2*(1.f/512.f) - mu*mu;
            smu[l] = mu;
            srs[l] = rsqrtf(var + 1e-5f);
        }
    }
    __syncthreads();
    float og = og_[e*DD+d], ob = ob_[e*DD+d];
    const float* zrow = g_z + (size_t)(e*BB+b)*LL*DD + d;
    float pooled = 0.f;
    #pragma unroll 7
    for (int l = 0; l < LL; l++){
        float v = sv[l*DD + d];
        float yn = (v - smu[l])*srs[l]*og + ob;
        float z = zrow[l*DD];
        pooled += yn * (z / (1.f + __expf(-z)));
    }
    pooled *= (1.f/49.f);
    float2 ss = blockReduce2(pooled, pooled*pooled);
    float mu = ss.x*(1.f/512.f);
    float var = ss.y*(1.f/512.f) - mu*mu;
    float rs = rsqrtf(var + 1e-5f);
    g_allout[(e*BB+b)*DD + d] = (pooled - mu)*rs*ng_[e*DD+d] + nb_[e*DD+d];
}

// ---------------- K8: mixture + aux loss output -----------------------------
__global__ void k_mix(float* __restrict__ out, int out_size){
    int b = blockIdx.x, d = threadIdx.x;
    int   a0 = g_topi[b*2], a1 = g_topi[b*2+1];
    float v0 = g_topv[b*2], v1 = g_topv[b*2+1];
    out[b*DD + d] = v0*g_allout[(a0*BB+b)*DD + d] + v1*g_allout[(a1*BB+b)*DD + d];
    if (b == 0 && d == 0 && out_size > BB*DD) out[BB*DD] = g_aux;
}

// ---------------- launch ----------------------------------------------------
extern "C" void kernel_launch(void* const* d_in, const int* in_sizes, int n_in,
                              void* d_out, int out_size){
    const float* x    = (const float*)d_in[0];
    const float* wg   = (const float*)d_in[1];
    const float* bg   = (const float*)d_in[2];
    const float* ipw  = (const float*)d_in[3];
    const float* ipb  = (const float*)d_in[4];
    const float* cw   = (const float*)d_in[5];
    const float* cb   = (const float*)d_in[6];
    const float* xpw  = (const float*)d_in[7];
    const float* dtw  = (const float*)d_in[8];
    const float* dtb  = (const float*)d_in[9];
    const float* alog = (const float*)d_in[10];
    const float* ds   = (const float*)d_in[11];
    const float* ong  = (const float*)d_in[12];
    const float* onb  = (const float*)d_in[13];
    const float* ng   = (const float*)d_in[14];
    const float* nb   = (const float*)d_in[15];
    float* out = (float*)d_out;

    cudaFuncSetAttribute(k_inproj,   cudaFuncAttributeMaxDynamicSharedMemorySize, IP_SMEM);
    cudaFuncSetAttribute(k_xdblscan, cudaFuncAttributeMaxDynamicSharedMemorySize, XD_SMEM_BYTES);
    cudaFuncSetAttribute(k_combine,  cudaFuncAttributeMaxDynamicSharedMemorySize, CB_SMEM);

    k_gate    <<<32, 512>>>(x, wg, bg);
    k_gatefin <<<1, 32>>>();
    k_inproj  <<<dim3(32,4), 256, IP_SMEM>>>(x, ipw, ipb, cw, cb);
    k_xdblscan<<<512, 512, XD_SMEM_BYTES>>>(xpw, dtw, dtb, alog, ds);
    k_combine <<<dim3(32,4), 512, CB_SMEM>>>(ong, onb, ng, nb);
    k_mix     <<<32, 512>>>(out, out_size);
}

// round 5
// speedup vs baseline: 17.5999x; 1.8022x over previous
#include <cuda_runtime.h>
#include <math.h>

// Problem constants
#define EE  4      // experts
#define BB  32     // batch
#define HH  7
#define LL  49     // H*W
#define DD  512    // dim
#define C2  1024   // 2*dim
#define RR  32     // DT_RANK
#define NS  16     // N_STATE
#define KDn 4      // directions
#define NSLOT (BB*2)   // 64 selected (b, expert) slots

// ---------------- scratch (device globals; no allocation allowed) ----------
__device__ float g_z [EE*BB*LL*DD];          // z half of in_proj [e][b][l][d]
__device__ float g_xs[EE*BB*KDn*LL*DD];      // 4-direction scan inputs
__device__ float g_ys[EE*BB*KDn*LL*DD];      // scan outputs
__device__ float g_raw[BB*EE];
__device__ float g_aux;
__device__ int   g_topi[NSLOT];              // slot s -> expert  (b = s>>1)
__device__ float g_topv[NSLOT];              // slot s -> gate coeff
__device__ float g_allout[NSLOT*DD];         // slot-indexed expert outputs

// ---------------- f32x2 packed FMA helpers (sm_103a) -----------------------
__device__ __forceinline__ unsigned long long pk2(float lo, float hi){
    unsigned long long r;
    asm("mov.b64 %0, {%1, %2};" : "=l"(r) : "f"(lo), "f"(hi));
    return r;
}
__device__ __forceinline__ void fma2(unsigned long long& d, unsigned long long a, unsigned long long b){
    asm("fma.rn.f32x2 %0, %1, %2, %0;" : "+l"(d) : "l"(a), "l"(b));
}
__device__ __forceinline__ void upk2(unsigned long long v, float& lo, float& hi){
    asm("mov.b64 {%0, %1}, %2;" : "=f"(lo), "=f"(hi) : "l"(v));
}
__device__ __forceinline__ float ex2f(float x){
    float r; asm("ex2.approx.f32 %0, %1;" : "=f"(r) : "f"(x)); return r;
}
__device__ __forceinline__ float lg2f(float x){
    float r; asm("lg2.approx.f32 %0, %1;" : "=f"(r) : "f"(x)); return r;
}

// ---------------- K1: gate logits + softmax per batch ----------------------
__global__ void k_gate(const float* __restrict__ x, const float* __restrict__ wg,
                       const float* __restrict__ bg){
    int b = blockIdx.x, tid = threadIdx.x;           // 512 threads, tid = channel
    const float* xb = x + (size_t)b*LL*DD + tid;
    float s = 0.f;
    #pragma unroll 7
    for (int l = 0; l < LL; l++) s += xb[l*DD];
    s *= (1.f/49.f);
    float p0 = s*wg[tid*EE+0], p1 = s*wg[tid*EE+1];
    float p2 = s*wg[tid*EE+2], p3 = s*wg[tid*EE+3];
    #pragma unroll
    for (int o = 16; o; o >>= 1){
        p0 += __shfl_xor_sync(0xffffffffu, p0, o);
        p1 += __shfl_xor_sync(0xffffffffu, p1, o);
        p2 += __shfl_xor_sync(0xffffffffu, p2, o);
        p3 += __shfl_xor_sync(0xffffffffu, p3, o);
    }
    __shared__ float sp[16][4];
    int w = tid >> 5, lane = tid & 31;
    if (lane == 0){ sp[w][0]=p0; sp[w][1]=p1; sp[w][2]=p2; sp[w][3]=p3; }
    __syncthreads();
    if (tid == 0){
        float lg[4];
        for (int e = 0; e < 4; e++){
            float a = bg[e];
            for (int ww = 0; ww < 16; ww++) a += sp[ww][e];
            lg[e] = a;
        }
        float m = fmaxf(fmaxf(lg[0],lg[1]), fmaxf(lg[2],lg[3]));
        float ex[4], se = 0.f;
        for (int e = 0; e < 4; e++){ ex[e] = expf(lg[e]-m); se += ex[e]; }
        for (int e = 0; e < 4; e++) g_raw[b*4+e] = ex[e]/se;
    }
}

// ---------------- K2: top-k, mask, denom, aux loss, gate scores ------------
__global__ void k_gatefin(){
    __shared__ float sraw[32][4];
    __shared__ float smask[32][4];
    __shared__ float sden[4];
    int b = threadIdx.x;  // 32 threads
    float r[4];
    #pragma unroll
    for (int e = 0; e < 4; e++){ r[e] = g_raw[b*4+e]; sraw[b][e] = r[e]; }
    int i0 = 0; float m0 = r[0];
    #pragma unroll
    for (int e = 1; e < 4; e++) if (r[e] > m0){ m0 = r[e]; i0 = e; }
    int i1 = -1; float m1 = -1e30f;
    #pragma unroll
    for (int e = 0; e < 4; e++) if (e != i0 && r[e] > m1){ m1 = r[e]; i1 = e; }
    #pragma unroll
    for (int e = 0; e < 4; e++) smask[b][e] = (e==i0 || e==i1) ? 1.f : 0.f;
    __syncthreads();
    if (b == 0){
        float aux = 0.f;
        for (int e = 0; e < 4; e++){
            float ds = 0.f, imp = 0.f, ld = 0.f;
            for (int bb = 0; bb < 32; bb++){
                ds  += sraw[bb][e]*smask[bb][e];
                imp += sraw[bb][e];
                ld  += smask[bb][e];
            }
            sden[e] = ds + 1e-6f;
            imp *= (1.f/32.f); ld *= (1.f/32.f);
            aux += (ld-imp)*(ld-imp);
        }
        g_aux = 0.01f * aux * 0.25f;
    }
    __syncthreads();
    const float cap = 40.f;   // int(1.25*32)
    float s0 = r[i0]*cap/sden[i0];
    float s1 = r[i1]*cap/sden[i1];
    int a0 = i0, a1 = i1; float v0 = s0, v1 = s1;
    if (v1 > v0 || (v1 == v0 && a1 < a0)){
        int t = a0; a0 = a1; a1 = t;
        float tv = v0; v0 = v1; v1 = tv;
    }
    g_topi[b*2] = a0; g_topi[b*2+1] = a1;
    g_topv[b*2] = v0; g_topv[b*2+1] = v1;
}

// ---------------- K3: in_proj GEMM + fused depthwise conv + scatter --------
// grid (64 slots, 2 roles) x 256 threads. Role 0: xin cols [0,512) + conv;
// role 1: z cols [512,1024) -> g_z. Thread: 2 cols x (25|24) l-tile, f32x2.
#define IP_SMEM (2*LL*DD*4)   // 200704 (role 0 uses both halves)
__global__ void __launch_bounds__(256, 1)
k_inproj(const float* __restrict__ x, const float* __restrict__ Wi,
         const float* __restrict__ bi, const float* __restrict__ cw,
         const float* __restrict__ cb){
    extern __shared__ float sxh[];     // [0, 49*512): x rows
    float* sxin = sxh + LL*DD;         // role 0: conv input staging
    int s = blockIdx.x, role = blockIdx.y, tid = threadIdx.x;
    int b = s >> 1;
    int e = g_topi[s];
    const float* xb = x + (size_t)b*LL*DD;
    for (int i = tid; i < LL*DD; i += 256) sxh[i] = xb[i];
    __syncthreads();
    const float* We = Wi + (size_t)e*DD*C2 + role*DD;
    int c0 = tid*2;
    float* zout = g_z + (size_t)(e*BB+b)*LL*DD;
    float2 bia = *(const float2*)(bi + e*C2 + role*DD + c0);
    #pragma unroll
    for (int lt = 0; lt < 2; lt++){
        const int base = lt*25;
        const int nl = lt ? 24 : 25;
        unsigned long long acc[25];
        #pragma unroll
        for (int i = 0; i < 25; i++) acc[i] = 0ull;
        #pragma unroll 2
        for (int kk = 0; kk < DD; kk++){
            float2 w = *(const float2*)(We + (size_t)kk*C2 + c0);
            unsigned long long wp = pk2(w.x, w.y);
            const float* xr = sxh + base*DD + kk;
            #pragma unroll
            for (int i = 0; i < 25; i++){
                if (i < nl){
                    float xk = xr[i*DD];
                    fma2(acc[i], wp, pk2(xk, xk));
                }
            }
        }
        #pragma unroll
        for (int i = 0; i < 25; i++){
            if (i < nl){
                int l = base + i;
                float r0, r1;
                upk2(acc[i], r0, r1);
                float2 o = make_float2(r0 + bia.x, r1 + bia.y);
                if (role == 0) *(float2*)(sxin + (size_t)l*DD + c0) = o;
                else           *(float2*)(zout + (size_t)l*DD + c0) = o;
            }
        }
    }
    if (role != 0) return;
    __syncthreads();
    // ---- depthwise 3x3 conv + silu + scatter; thread handles d = tid, tid+256
    float* xsb = g_xs + (size_t)(e*BB+b)*KDn*LL*DD;
    #pragma unroll
    for (int half = 0; half < 2; half++){
        int d = tid + half*256;
        float w9[9];
        #pragma unroll
        for (int t = 0; t < 9; t++) w9[t] = cw[(e*DD+d)*9 + t];
        float bias = cb[e*DD+d];
        float row[3][7];
        #pragma unroll
        for (int j = 0; j < 7; j++){
            row[0][j] = sxin[(0*7+j)*DD + d];
            row[1][j] = sxin[(1*7+j)*DD + d];
        }
        #pragma unroll
        for (int i = 0; i < 7; i++){
            if (i < 6){
                #pragma unroll
                for (int j = 0; j < 7; j++)
                    row[(i+1)%3][j] = sxin[((i+1)*7+j)*DD + d];
            }
            const float* rm = (i > 0) ? row[(i-1)%3] : nullptr;
            const float* rc = row[i%3];
            const float* rp = (i < 6) ? row[(i+1)%3] : nullptr;
            #pragma unroll
            for (int j = 0; j < 7; j++){
                float a = bias;
                #pragma unroll
                for (int dj = 0; dj < 3; dj++){
                    int jj = j + dj - 1;
                    if (jj < 0 || jj > 6) continue;
                    if (i > 0) a += rm[jj]*w9[0*3+dj];
                    a += rc[jj]*w9[1*3+dj];
                    if (i < 6) a += rp[jj]*w9[2*3+dj];
                }
                float v = a / (1.f + __expf(-a));   // silu
                int l  = i*7 + j;
                int lv = j*7 + i;
                xsb[(0*LL + l       )*DD + d] = v;
                xsb[(1*LL + (48-l)  )*DD + d] = v;
                xsb[(2*LL + lv      )*DD + d] = v;
                xsb[(3*LL + (48-lv) )*DD + d] = v;
            }
        }
    }
}

// ---------------- K5: fused x_dbl + dt_proj + selective scan ---------------
// grid = 64 slots x 4 k = 256 blocks, 512 threads.
#define DTW_S 513
#define XD_SMEM_BYTES ((LL*DD + 64*DD)*4)   // 100352 + 131072 = 231424
__global__ void __launch_bounds__(512, 1)
k_xdblscan(const float* __restrict__ xpw_, const float* __restrict__ dtw_,
           const float* __restrict__ dtb_, const float* __restrict__ alog_,
           const float* __restrict__ ds_){
    extern __shared__ float sm[];
    float* sx  = sm;                 // LL*DD floats
    float* wsm = sm + LL*DD;         // 64 x 512, XOR-swizzled (phase A)
    float* dtwT = sm + LL*DD;        // 32 x DTW_S (phase B) aliases wsm
    float* sdbl = dtwT + 32*DTW_S;   // 49 x 32 dt-rank
    float* sBC  = sdbl + LL*32;      // 49 x 32 (B | C)
    int idx = blockIdx.x;
    int k = idx & 3, s = idx >> 2;
    int b = s >> 1;
    int e = g_topi[s];
    int tid = threadIdx.x;
    int lane = tid & 31, w = tid >> 5;

    const float* xsrow = g_xs + (size_t)((e*BB+b)*KDn + k)*LL*DD;
    const float* xpw = xpw_ + (size_t)((e*KDn+k)*64)*DD;   // [c][d]
    const float* dtw = dtw_ + (size_t)((e*KDn+k)*DD)*RR;   // [d][r]
    const float* dtb = dtb_ + (e*KDn+k)*DD;
    float* ysout = g_ys + (size_t)((e*BB+b)*KDn + k)*LL*DD;

    // load sx tile (coalesced) + xpw into XOR-swizzled smem
    for (int i = tid; i < LL*DD; i += 512) sx[i] = xsrow[i];
    for (int i = tid; i < 64*DD; i += 512){
        int c = i >> 9, dd = i & 511;
        int g = dd >> 2;
        wsm[c*DD + ((((g ^ (c & 7)) << 2)) | (dd & 3))] = xpw[i];
    }
    __syncthreads();

    // ---- Phase A: x_dbl[c][l] = sum_d sx[l][d]*w[c][d], split-K ----
    int wg = w & 7;            // l-group: wg*6..wg*6+5 (wg==0 also handles l=48)
    int ks = w >> 3;           // K-split half
    int kk0 = ks << 8;
    int l0 = wg*6;
    int nl = (wg == 0) ? 7 : 6;
    int c0 = lane, c1 = lane + 32;
    unsigned long long a0[7], a1[7];
    #pragma unroll
    for (int j = 0; j < 7; j++){ a0[j] = 0ull; a1[j] = 0ull; }
    const float* w0base = wsm + c0*DD;
    const float* w1base = wsm + c1*DD;
    int sw = (lane & 7) << 2;     // xor pattern
    #pragma unroll 4
    for (int t = 0; t < 64; t++){
        int kk = kk0 + t*4;
        float4 w0 = *(const float4*)(w0base + (kk ^ sw));
        float4 w1 = *(const float4*)(w1base + (kk ^ sw));
        unsigned long long w0a = pk2(w0.x, w0.y), w0b = pk2(w0.z, w0.w);
        unsigned long long w1a = pk2(w1.x, w1.y), w1b = pk2(w1.z, w1.w);
        #pragma unroll
        for (int j = 0; j < 7; j++){
            if (j < nl){
                int l = (j == 6) ? 48 : (l0 + j);
                float4 xv = *(const float4*)(sx + l*DD + kk);
                unsigned long long xa = pk2(xv.x, xv.y), xb = pk2(xv.z, xv.w);
                fma2(a0[j], w0a, xa); fma2(a0[j], w0b, xb);
                fma2(a1[j], w1a, xa); fma2(a1[j], w1b, xb);
            }
        }
    }
    __syncthreads();   // all wsm/sx phase-A reads done; wsm region reusable

    // stage: split-K half 0 writes, half 1 adds
    if (ks == 0){
        #pragma unroll
        for (int j = 0; j < 7; j++){
            if (j < nl){
                int l = (j == 6) ? 48 : (l0 + j);
                float lo, hi;
                upk2(a0[j], lo, hi); sdbl[l*32 + lane] = lo + hi;
                upk2(a1[j], lo, hi); sBC [l*32 + lane] = lo + hi;
            }
        }
    }
    __syncthreads();
    if (ks == 1){
        #pragma unroll
        for (int j = 0; j < 7; j++){
            if (j < nl){
                int l = (j == 6) ? 48 : (l0 + j);
                float lo, hi;
                upk2(a0[j], lo, hi); sdbl[l*32 + lane] += lo + hi;
                upk2(a1[j], lo, hi); sBC [l*32 + lane] += lo + hi;
            }
        }
    }
    // load dtw transposed into dtwT (disjoint from sdbl/sBC)
    for (int i = tid; i < DD*RR; i += 512){
        int dd = i >> 5, r = i & 31;
        dtwT[r*DTW_S + dd] = dtw[i];
    }
    __syncthreads();

    // ---- Phase B + scan, thread dd = tid owns channel dd ----
    int dd = tid;
    float bias = dtb[dd];
    float A[NS];
    {
        const float4* al = (const float4*)(alog_ + ((size_t)((e*KDn+k)*DD) + dd)*NS);
        const float L2E = 1.44269504088896f;
        #pragma unroll
        for (int q = 0; q < 4; q++){
            float4 v = al[q];
            A[q*4+0] = -__expf(v.x)*L2E; A[q*4+1] = -__expf(v.y)*L2E;
            A[q*4+2] = -__expf(v.z)*L2E; A[q*4+3] = -__expf(v.w)*L2E;
        }
    }
    float Dd = ds_[(e*KDn+k)*DD + dd];
    float h[NS];
    #pragma unroll
    for (int n = 0; n < NS; n++) h[n] = 0.f;

    const float L2E = 1.44269504088896f;
    const float LN2 = 0.69314718055995f;
    #pragma unroll 1
    for (int lg = 0; lg < 13; lg++){
        int l0b = lg*4;
        int nlb = (lg < 12) ? 4 : 1;
        float q0 = bias, q1 = bias, q2 = bias, q3 = bias;
        const float4* s0 = (const float4*)(sdbl + (l0b    )*32);
        const float4* s1 = (const float4*)(sdbl + (l0b + 1)*32);
        const float4* s2 = (const float4*)(sdbl + (l0b + 2)*32);
        const float4* s3 = (const float4*)(sdbl + (l0b + 3)*32);
        if (nlb == 4){
            #pragma unroll
            for (int rc = 0; rc < 8; rc++){
                float w0 = dtwT[(4*rc+0)*DTW_S + dd];
                float w1 = dtwT[(4*rc+1)*DTW_S + dd];
                float w2 = dtwT[(4*rc+2)*DTW_S + dd];
                float w3 = dtwT[(4*rc+3)*DTW_S + dd];
                float4 v0 = s0[rc], v1 = s1[rc], v2 = s2[rc], v3 = s3[rc];
                q0 += v0.x*w0 + v0.y*w1 + v0.z*w2 + v0.w*w3;
                q1 += v1.x*w0 + v1.y*w1 + v1.z*w2 + v1.w*w3;
                q2 += v2.x*w0 + v2.y*w1 + v2.z*w2 + v2.w*w3;
                q3 += v3.x*w0 + v3.y*w1 + v3.z*w2 + v3.w*w3;
            }
        } else {
            #pragma unroll
            for (int rc = 0; rc < 8; rc++){
                float w0 = dtwT[(4*rc+0)*DTW_S + dd];
                float w1 = dtwT[(4*rc+1)*DTW_S + dd];
                float w2 = dtwT[(4*rc+2)*DTW_S + dd];
                float w3 = dtwT[(4*rc+3)*DTW_S + dd];
                float4 v0 = s0[rc];
                q0 += v0.x*w0 + v0.y*w1 + v0.z*w2 + v0.w*w3;
            }
        }
        float dts[4] = {q0, q1, q2, q3};
        #pragma unroll
        for (int j = 0; j < 4; j++){
            if (j >= nlb) break;
            int l = l0b + j;
            float a = dts[j];
            // softplus via MUFU: max(a,0) + ln2*log2(1 + 2^(-|a|*log2e))
            float dtv = fmaxf(a, 0.f) + LN2*lg2f(1.f + ex2f(-fabsf(a)*L2E));
            float xv = sx[l*DD + dd];
            float dx = dtv*xv;
            const float4* bc4 = (const float4*)(sBC + l*32);
            float y = 0.f;
            #pragma unroll
            for (int q = 0; q < 4; q++){
                float4 Bv = bc4[q];
                float4 Cv = bc4[4+q];
                h[4*q+0] = h[4*q+0]*ex2f(dtv*A[4*q+0]) + dx*Bv.x;  y += h[4*q+0]*Cv.x;
                h[4*q+1] = h[4*q+1]*ex2f(dtv*A[4*q+1]) + dx*Bv.y;  y += h[4*q+1]*Cv.y;
                h[4*q+2] = h[4*q+2]*ex2f(dtv*A[4*q+2]) + dx*Bv.z;  y += h[4*q+2]*Cv.z;
                h[4*q+3] = h[4*q+3]*ex2f(dtv*A[4*q+3]) + dx*Bv.w;  y += h[4*q+3]*Cv.w;
            }
            ysout[l*DD + dd] = y + Dd*xv;
        }
    }
}

// ---------------- block reduction (sum, sumsq) over 512 threads ------------
__device__ __forceinline__ float2 blockReduce2(float a, float b){
    __shared__ float sa[16], sb[16];
    __shared__ float2 res;
    int lane = threadIdx.x & 31, w = threadIdx.x >> 5;
    #pragma unroll
    for (int o = 16; o; o >>= 1){
        a += __shfl_xor_sync(0xffffffffu, a, o);
        b += __shfl_xor_sync(0xffffffffu, b, o);
    }
    __syncthreads();
    if (lane == 0){ sa[w] = a; sb[w] = b; }
    __syncthreads();
    if (w == 0){
        a = (lane < 16) ? sa[lane] : 0.f;
        b = (lane < 16) ? sb[lane] : 0.f;
        #pragma unroll
        for (int o = 8; o; o >>= 1){
            a += __shfl_xor_sync(0xffffffffu, a, o);
            b += __shfl_xor_sync(0xffffffffu, b, o);
        }
        if (lane == 0){ res.x = a; res.y = b; }
    }
    __syncthreads();
    return res;
}

// ---------------- K7: combine directions + LN + silu(z) gate + pool + LN ---
#define CB_SMEM ((LL*DD + 128)*4)
__global__ void __launch_bounds__(512, 1)
k_combine(const float* __restrict__ og_, const float* __restrict__ ob_,
          const float* __restrict__ ng_, const float* __restrict__ nb_){
    extern __shared__ float sv[];        // 49*512 + mu/rs
    float* smu = sv + LL*DD;             // 49
    float* srs = smu + 56;               // 49
    int s = blockIdx.x, d = threadIdx.x;   // 64 slots, 512 threads
    int b = s >> 1;
    int e = g_topi[s];
    size_t yb = (size_t)(e*BB+b)*KDn*LL*DD;
    #pragma unroll 1
    for (int l = 0; l < LL; l++){
        int i = l/7, j = l - 7*i;
        int lv = j*7 + i;
        float v = g_ys[yb + (0*LL + l       )*DD + d]
                + g_ys[yb + (1*LL + (48-l)  )*DD + d]
                + g_ys[yb + (2*LL + lv      )*DD + d]
                + g_ys[yb + (3*LL + (48-lv) )*DD + d];
        sv[l*DD + d] = v;
    }
    __syncthreads();
    int w = d >> 5, lane = d & 31;
    for (int l = w; l < LL; l += 16){
        float a = 0.f, s2 = 0.f;
        #pragma unroll
        for (int jj = 0; jj < 16; jj++){
            float xv = sv[l*DD + lane + 32*jj];
            a += xv; s2 += xv*xv;
        }
        #pragma unroll
        for (int o = 16; o; o >>= 1){
            a  += __shfl_xor_sync(0xffffffffu, a, o);
            s2 += __shfl_xor_sync(0xffffffffu, s2, o);
        }
        if (lane == 0){
            float mu = a*(1.f/512.f);
            float var = s2*(1.f/512.f) - mu*mu;
            smu[l] = mu;
            srs[l] = rsqrtf(var + 1e-5f);
        }
    }
    __syncthreads();
    float og = og_[e*DD+d], ob = ob_[e*DD+d];
    const float* zrow = g_z + (size_t)(e*BB+b)*LL*DD + d;
    float pooled = 0.f;
    #pragma unroll 7
    for (int l = 0; l < LL; l++){
        float v = sv[l*DD + d];
        float yn = (v - smu[l])*srs[l]*og + ob;
        float z = zrow[l*DD];
        pooled += yn * (z / (1.f + __expf(-z)));
    }
    pooled *= (1.f/49.f);
    float2 ss = blockReduce2(pooled, pooled*pooled);
    float mu = ss.x*(1.f/512.f);
    float var = ss.y*(1.f/512.f) - mu*mu;
    float rs = rsqrtf(var + 1e-5f);
    g_allout[s*DD + d] = (pooled - mu)*rs*ng_[e*DD+d] + nb_[e*DD+d];
}

// ---------------- K8: mixture + aux loss output -----------------------------
__global__ void k_mix(float* __restrict__ out, int out_size){
    int b = blockIdx.x, d = threadIdx.x;
    float v0 = g_topv[b*2], v1 = g_topv[b*2+1];
    out[b*DD + d] = v0*g_allout[(b*2)*DD + d] + v1*g_allout[(b*2+1)*DD + d];
    if (b == 0 && d == 0 && out_size > BB*DD) out[BB*DD] = g_aux;
}

// ---------------- launch ----------------------------------------------------
extern "C" void kernel_launch(void* const* d_in, const int* in_sizes, int n_in,
                              void* d_out, int out_size){
    const float* x    = (const float*)d_in[0];
    const float* wg   = (const float*)d_in[1];
    const float* bg   = (const float*)d_in[2];
    const float* ipw  = (const float*)d_in[3];
    const float* ipb  = (const float*)d_in[4];
    const float* cw   = (const float*)d_in[5];
    const float* cb   = (const float*)d_in[6];
    const float* xpw  = (const float*)d_in[7];
    const float* dtw  = (const float*)d_in[8];
    const float* dtb  = (const float*)d_in[9];
    const float* alog = (const float*)d_in[10];
    const float* ds   = (const float*)d_in[11];
    const float* ong  = (const float*)d_in[12];
    const float* onb  = (const float*)d_in[13];
    const float* ng   = (const float*)d_in[14];
    const float* nb   = (const float*)d_in[15];
    float* out = (float*)d_out;

    cudaFuncSetAttribute(k_inproj,   cudaFuncAttributeMaxDynamicSharedMemorySize, IP_SMEM);
    cudaFuncSetAttribute(k_xdblscan, cudaFuncAttributeMaxDynamicSharedMemorySize, XD_SMEM_BYTES);
    cudaFuncSetAttribute(k_combine,  cudaFuncAttributeMaxDynamicSharedMemorySize, CB_SMEM);

    k_gate    <<<32, 512>>>(x, wg, bg);
    k_gatefin <<<1, 32>>>();
    k_inproj  <<<dim3(NSLOT, 2), 256, IP_SMEM>>>(x, ipw, ipb, cw, cb);
    k_xdblscan<<<NSLOT*KDn, 512, XD_SMEM_BYTES>>>(xpw, dtw, dtb, alog, ds);
    k_combine <<<NSLOT, 512, CB_SMEM>>>(ong, onb, ng, nb);
    k_mix     <<<BB, 512>>>(out, out_size);
}

// round 6
// speedup vs baseline: 18.0176x; 1.0237x over previous
#include <cuda_runtime.h>
#include <math.h>

// Problem constants
#define EE  4      // experts
#define BB  32     // batch
#define HH  7
#define LL  49     // H*W
#define DD  512    // dim
#define C2  1024   // 2*dim
#define RR  32     // DT_RANK
#define NS  16     // N_STATE
#define KDn 4      // directions
#define NSLOT (BB*2)   // 64 selected (b, expert) slots

// ---------------- scratch (device globals; no allocation allowed) ----------
__device__ float g_z [EE*BB*LL*DD];          // z half of in_proj [e][b][l][d]
__device__ float g_xs[EE*BB*KDn*LL*DD];      // 4-direction scan inputs
__device__ float g_ys[EE*BB*KDn*LL*DD];      // scan outputs
__device__ float g_raw[BB*EE];
__device__ float g_aux;
__device__ int   g_topi[NSLOT];              // slot s -> expert  (b = s>>1)
__device__ float g_topv[NSLOT];              // slot s -> gate coeff
__device__ float g_allout[NSLOT*DD];         // slot-indexed expert outputs

// ---------------- f32x2 packed FMA helpers (sm_103a) -----------------------
__device__ __forceinline__ unsigned long long pk2(float lo, float hi){
    unsigned long long r;
    asm("mov.b64 %0, {%1, %2};" : "=l"(r) : "f"(lo), "f"(hi));
    return r;
}
__device__ __forceinline__ void fma2(unsigned long long& d, unsigned long long a, unsigned long long b){
    asm("fma.rn.f32x2 %0, %1, %2, %0;" : "+l"(d) : "l"(a), "l"(b));
}
__device__ __forceinline__ void upk2(unsigned long long v, float& lo, float& hi){
    asm("mov.b64 {%0, %1}, %2;" : "=f"(lo), "=f"(hi) : "l"(v));
}
__device__ __forceinline__ float ex2f(float x){
    float r; asm("ex2.approx.f32 %0, %1;" : "=f"(r) : "f"(x)); return r;
}
__device__ __forceinline__ float lg2f(float x){
    float r; asm("lg2.approx.f32 %0, %1;" : "=f"(r) : "f"(x)); return r;
}

// ---------------- K1: gate logits + softmax per batch ----------------------
__global__ void k_gate(const float* __restrict__ x, const float* __restrict__ wg,
                       const float* __restrict__ bg){
    int b = blockIdx.x, tid = threadIdx.x;           // 512 threads, tid = channel
    const float* xb = x + (size_t)b*LL*DD + tid;
    float s = 0.f;
    #pragma unroll 7
    for (int l = 0; l < LL; l++) s += xb[l*DD];
    s *= (1.f/49.f);
    float p0 = s*wg[tid*EE+0], p1 = s*wg[tid*EE+1];
    float p2 = s*wg[tid*EE+2], p3 = s*wg[tid*EE+3];
    #pragma unroll
    for (int o = 16; o; o >>= 1){
        p0 += __shfl_xor_sync(0xffffffffu, p0, o);
        p1 += __shfl_xor_sync(0xffffffffu, p1, o);
        p2 += __shfl_xor_sync(0xffffffffu, p2, o);
        p3 += __shfl_xor_sync(0xffffffffu, p3, o);
    }
    __shared__ float sp[16][4];
    int w = tid >> 5, lane = tid & 31;
    if (lane == 0){ sp[w][0]=p0; sp[w][1]=p1; sp[w][2]=p2; sp[w][3]=p3; }
    __syncthreads();
    if (tid == 0){
        float lg[4];
        for (int e = 0; e < 4; e++){
            float a = bg[e];
            for (int ww = 0; ww < 16; ww++) a += sp[ww][e];
            lg[e] = a;
        }
        float m = fmaxf(fmaxf(lg[0],lg[1]), fmaxf(lg[2],lg[3]));
        float ex[4], se = 0.f;
        for (int e = 0; e < 4; e++){ ex[e] = expf(lg[e]-m); se += ex[e]; }
        for (int e = 0; e < 4; e++) g_raw[b*4+e] = ex[e]/se;
    }
}

// ---------------- K2: top-k, mask, denom, aux loss, gate scores ------------
__global__ void k_gatefin(){
    __shared__ float sraw[32][4];
    __shared__ float smask[32][4];
    __shared__ float sden[4];
    int b = threadIdx.x;  // 32 threads
    float r[4];
    #pragma unroll
    for (int e = 0; e < 4; e++){ r[e] = g_raw[b*4+e]; sraw[b][e] = r[e]; }
    int i0 = 0; float m0 = r[0];
    #pragma unroll
    for (int e = 1; e < 4; e++) if (r[e] > m0){ m0 = r[e]; i0 = e; }
    int i1 = -1; float m1 = -1e30f;
    #pragma unroll
    for (int e = 0; e < 4; e++) if (e != i0 && r[e] > m1){ m1 = r[e]; i1 = e; }
    #pragma unroll
    for (int e = 0; e < 4; e++) smask[b][e] = (e==i0 || e==i1) ? 1.f : 0.f;
    __syncthreads();
    if (b == 0){
        float aux = 0.f;
        for (int e = 0; e < 4; e++){
            float ds = 0.f, imp = 0.f, ld = 0.f;
            for (int bb = 0; bb < 32; bb++){
                ds  += sraw[bb][e]*smask[bb][e];
                imp += sraw[bb][e];
                ld  += smask[bb][e];
            }
            sden[e] = ds + 1e-6f;
            imp *= (1.f/32.f); ld *= (1.f/32.f);
            aux += (ld-imp)*(ld-imp);
        }
        g_aux = 0.01f * aux * 0.25f;
    }
    __syncthreads();
    const float cap = 40.f;   // int(1.25*32)
    float s0 = r[i0]*cap/sden[i0];
    float s1 = r[i1]*cap/sden[i1];
    int a0 = i0, a1 = i1; float v0 = s0, v1 = s1;
    if (v1 > v0 || (v1 == v0 && a1 < a0)){
        int t = a0; a0 = a1; a1 = t;
        float tv = v0; v0 = v1; v1 = tv;
    }
    g_topi[b*2] = a0; g_topi[b*2+1] = a1;
    g_topv[b*2] = v0; g_topv[b*2+1] = v1;
}

// ---------------- K3: in_proj GEMM + fused depthwise conv + scatter --------
// grid (64 slots, 2 roles) x 256 threads. Role 0: xin cols [0,512) + conv;
// role 1: z cols [512,1024) -> g_z. Thread: 2 cols x (25|24) l-tile, f32x2.
#define IP_SMEM (2*LL*DD*4)   // 200704 (role 0 uses both halves)
__global__ void __launch_bounds__(256, 1)
k_inproj(const float* __restrict__ x, const float* __restrict__ Wi,
         const float* __restrict__ bi, const float* __restrict__ cw,
         const float* __restrict__ cb){
    extern __shared__ float sxh[];     // [0, 49*512): x rows
    float* sxin = sxh + LL*DD;         // role 0: conv input staging
    int s = blockIdx.x, role = blockIdx.y, tid = threadIdx.x;
    int b = s >> 1;
    int e = g_topi[s];
    const float* xb = x + (size_t)b*LL*DD;
    for (int i = tid; i < LL*DD; i += 256) sxh[i] = xb[i];
    __syncthreads();
    const float* We = Wi + (size_t)e*DD*C2 + role*DD;
    int c0 = tid*2;
    float* zout = g_z + (size_t)(e*BB+b)*LL*DD;
    float2 bia = *(const float2*)(bi + e*C2 + role*DD + c0);
    #pragma unroll
    for (int lt = 0; lt < 2; lt++){
        const int base = lt*25;
        const int nl = lt ? 24 : 25;
        unsigned long long acc[25];
        #pragma unroll
        for (int i = 0; i < 25; i++) acc[i] = 0ull;
        #pragma unroll 2
        for (int kk = 0; kk < DD; kk++){
            float2 w = *(const float2*)(We + (size_t)kk*C2 + c0);
            unsigned long long wp = pk2(w.x, w.y);
            const float* xr = sxh + base*DD + kk;
            #pragma unroll
            for (int i = 0; i < 25; i++){
                if (i < nl){
                    float xk = xr[i*DD];
                    fma2(acc[i], wp, pk2(xk, xk));
                }
            }
        }
        #pragma unroll
        for (int i = 0; i < 25; i++){
            if (i < nl){
                int l = base + i;
                float r0, r1;
                upk2(acc[i], r0, r1);
                float2 o = make_float2(r0 + bia.x, r1 + bia.y);
                if (role == 0) *(float2*)(sxin + (size_t)l*DD + c0) = o;
                else           *(float2*)(zout + (size_t)l*DD + c0) = o;
            }
        }
    }
    if (role != 0) return;
    __syncthreads();
    // ---- depthwise 3x3 conv + silu + scatter; thread handles d = tid, tid+256
    float* xsb = g_xs + (size_t)(e*BB+b)*KDn*LL*DD;
    #pragma unroll
    for (int half = 0; half < 2; half++){
        int d = tid + half*256;
        float w9[9];
        #pragma unroll
        for (int t = 0; t < 9; t++) w9[t] = cw[(e*DD+d)*9 + t];
        float bias = cb[e*DD+d];
        float row[3][7];
        #pragma unroll
        for (int j = 0; j < 7; j++){
            row[0][j] = sxin[(0*7+j)*DD + d];
            row[1][j] = sxin[(1*7+j)*DD + d];
        }
        #pragma unroll
        for (int i = 0; i < 7; i++){
            if (i < 6){
                #pragma unroll
                for (int j = 0; j < 7; j++)
                    row[(i+1)%3][j] = sxin[((i+1)*7+j)*DD + d];
            }
            const float* rm = (i > 0) ? row[(i-1)%3] : nullptr;
            const float* rc = row[i%3];
            const float* rp = (i < 6) ? row[(i+1)%3] : nullptr;
            #pragma unroll
            for (int j = 0; j < 7; j++){
                float a = bias;
                #pragma unroll
                for (int dj = 0; dj < 3; dj++){
                    int jj = j + dj - 1;
                    if (jj < 0 || jj > 6) continue;
                    if (i > 0) a += rm[jj]*w9[0*3+dj];
                    a += rc[jj]*w9[1*3+dj];
                    if (i < 6) a += rp[jj]*w9[2*3+dj];
                }
                float v = a / (1.f + __expf(-a));   // silu
                int l  = i*7 + j;
                int lv = j*7 + i;
                xsb[(0*LL + l       )*DD + d] = v;
                xsb[(1*LL + (48-l)  )*DD + d] = v;
                xsb[(2*LL + lv      )*DD + d] = v;
                xsb[(3*LL + (48-lv) )*DD + d] = v;
            }
        }
    }
}

// ---------------- K5: fused x_dbl + dt_proj + selective scan ---------------
// grid = 64 slots x 4 k = 256 blocks, 512 threads.
#define DTW_S 513
#define XD_SMEM_BYTES ((LL*DD + 64*DD)*4)   // 100352 + 131072 = 231424
__global__ void __launch_bounds__(512, 1)
k_xdblscan(const float* __restrict__ xpw_, const float* __restrict__ dtw_,
           const float* __restrict__ dtb_, const float* __restrict__ alog_,
           const float* __restrict__ ds_){
    extern __shared__ float sm[];
    float* sx  = sm;                 // LL*DD floats
    float* wsm = sm + LL*DD;         // 64 x 512, XOR-swizzled (phase A)
    float* dtwT = sm + LL*DD;        // 32 x DTW_S (phase B) aliases wsm
    float* sdbl = dtwT + 32*DTW_S;   // 49 x 32 dt-rank
    float* sBC  = sdbl + LL*32;      // 49 x 32 (B | C)
    int idx = blockIdx.x;
    int k = idx & 3, s = idx >> 2;
    int b = s >> 1;
    int e = g_topi[s];
    int tid = threadIdx.x;
    int lane = tid & 31, w = tid >> 5;

    const float* xsrow = g_xs + (size_t)((e*BB+b)*KDn + k)*LL*DD;
    const float* xpw = xpw_ + (size_t)((e*KDn+k)*64)*DD;   // [c][d]
    const float* dtw = dtw_ + (size_t)((e*KDn+k)*DD)*RR;   // [d][r]
    const float* dtb = dtb_ + (e*KDn+k)*DD;
    float* ysout = g_ys + (size_t)((e*BB+b)*KDn + k)*LL*DD;

    // load sx tile (coalesced) + xpw into XOR-swizzled smem
    for (int i = tid; i < LL*DD; i += 512) sx[i] = xsrow[i];
    for (int i = tid; i < 64*DD; i += 512){
        int c = i >> 9, dd = i & 511;
        int g = dd >> 2;
        wsm[c*DD + ((((g ^ (c & 7)) << 2)) | (dd & 3))] = xpw[i];
    }
    __syncthreads();

    // ---- Phase A: x_dbl[c][l] = sum_d sx[l][d]*w[c][d], split-K ----
    int wg = w & 7;            // l-group: wg*6..wg*6+5 (wg==0 also handles l=48)
    int ks = w >> 3;           // K-split half
    int kk0 = ks << 8;
    int l0 = wg*6;
    int nl = (wg == 0) ? 7 : 6;
    int c0 = lane, c1 = lane + 32;
    unsigned long long a0[7], a1[7];
    #pragma unroll
    for (int j = 0; j < 7; j++){ a0[j] = 0ull; a1[j] = 0ull; }
    const float* w0base = wsm + c0*DD;
    const float* w1base = wsm + c1*DD;
    int sw = (lane & 7) << 2;     // xor pattern
    #pragma unroll 4
    for (int t = 0; t < 64; t++){
        int kk = kk0 + t*4;
        float4 w0 = *(const float4*)(w0base + (kk ^ sw));
        float4 w1 = *(const float4*)(w1base + (kk ^ sw));
        unsigned long long w0a = pk2(w0.x, w0.y), w0b = pk2(w0.z, w0.w);
        unsigned long long w1a = pk2(w1.x, w1.y), w1b = pk2(w1.z, w1.w);
        #pragma unroll
        for (int j = 0; j < 7; j++){
            if (j < nl){
                int l = (j == 6) ? 48 : (l0 + j);
                float4 xv = *(const float4*)(sx + l*DD + kk);
                unsigned long long xa = pk2(xv.x, xv.y), xb = pk2(xv.z, xv.w);
                fma2(a0[j], w0a, xa); fma2(a0[j], w0b, xb);
                fma2(a1[j], w1a, xa); fma2(a1[j], w1b, xb);
            }
        }
    }
    __syncthreads();   // all wsm/sx phase-A reads done; wsm region reusable

    // stage: split-K half 0 writes, half 1 adds
    if (ks == 0){
        #pragma unroll
        for (int j = 0; j < 7; j++){
            if (j < nl){
                int l = (j == 6) ? 48 : (l0 + j);
                float lo, hi;
                upk2(a0[j], lo, hi); sdbl[l*32 + lane] = lo + hi;
                upk2(a1[j], lo, hi); sBC [l*32 + lane] = lo + hi;
            }
        }
    }
    __syncthreads();
    if (ks == 1){
        #pragma unroll
        for (int j = 0; j < 7; j++){
            if (j < nl){
                int l = (j == 6) ? 48 : (l0 + j);
                float lo, hi;
                upk2(a0[j], lo, hi); sdbl[l*32 + lane] += lo + hi;
                upk2(a1[j], lo, hi); sBC [l*32 + lane] += lo + hi;
            }
        }
    }
    // load dtw transposed into dtwT (disjoint from sdbl/sBC)
    for (int i = tid; i < DD*RR; i += 512){
        int dd = i >> 5, r = i & 31;
        dtwT[r*DTW_S + dd] = dtw[i];
    }
    __syncthreads();

    // ---- Phase B + scan, thread dd = tid owns channel dd ----
    int dd = tid;
    float bias = dtb[dd];
    float A[NS];
    {
        const float4* al = (const float4*)(alog_ + ((size_t)((e*KDn+k)*DD) + dd)*NS);
        const float L2E = 1.44269504088896f;
        #pragma unroll
        for (int q = 0; q < 4; q++){
            float4 v = al[q];
            A[q*4+0] = -__expf(v.x)*L2E; A[q*4+1] = -__expf(v.y)*L2E;
            A[q*4+2] = -__expf(v.z)*L2E; A[q*4+3] = -__expf(v.w)*L2E;
        }
    }
    float Dd = ds_[(e*KDn+k)*DD + dd];
    float h[NS];
    #pragma unroll
    for (int n = 0; n < NS; n++) h[n] = 0.f;

    const float L2E = 1.44269504088896f;
    const float LN2 = 0.69314718055995f;
    #pragma unroll 1
    for (int lg = 0; lg < 13; lg++){
        int l0b = lg*4;
        int nlb = (lg < 12) ? 4 : 1;
        float q0 = bias, q1 = bias, q2 = bias, q3 = bias;
        const float4* s0 = (const float4*)(sdbl + (l0b    )*32);
        const float4* s1 = (const float4*)(sdbl + (l0b + 1)*32);
        const float4* s2 = (const float4*)(sdbl + (l0b + 2)*32);
        const float4* s3 = (const float4*)(sdbl + (l0b + 3)*32);
        if (nlb == 4){
            #pragma unroll
            for (int rc = 0; rc < 8; rc++){
                float w0 = dtwT[(4*rc+0)*DTW_S + dd];
                float w1 = dtwT[(4*rc+1)*DTW_S + dd];
                float w2 = dtwT[(4*rc+2)*DTW_S + dd];
                float w3 = dtwT[(4*rc+3)*DTW_S + dd];
                float4 v0 = s0[rc], v1 = s1[rc], v2 = s2[rc], v3 = s3[rc];
                q0 += v0.x*w0 + v0.y*w1 + v0.z*w2 + v0.w*w3;
                q1 += v1.x*w0 + v1.y*w1 + v1.z*w2 + v1.w*w3;
                q2 += v2.x*w0 + v2.y*w1 + v2.z*w2 + v2.w*w3;
                q3 += v3.x*w0 + v3.y*w1 + v3.z*w2 + v3.w*w3;
            }
        } else {
            #pragma unroll
            for (int rc = 0; rc < 8; rc++){
                float w0 = dtwT[(4*rc+0)*DTW_S + dd];
                float w1 = dtwT[(4*rc+1)*DTW_S + dd];
                float w2 = dtwT[(4*rc+2)*DTW_S + dd];
                float w3 = dtwT[(4*rc+3)*DTW_S + dd];
                float4 v0 = s0[rc];
                q0 += v0.x*w0 + v0.y*w1 + v0.z*w2 + v0.w*w3;
            }
        }
        float dts[4] = {q0, q1, q2, q3};
        #pragma unroll
        for (int j = 0; j < 4; j++){
            if (j >= nlb) break;
            int l = l0b + j;
            float a = dts[j];
            // softplus via MUFU: max(a,0) + ln2*log2(1 + 2^(-|a|*log2e))
            float dtv = fmaxf(a, 0.f) + LN2*lg2f(1.f + ex2f(-fabsf(a)*L2E));
            float xv = sx[l*DD + dd];
            float dx = dtv*xv;
            const float4* bc4 = (const float4*)(sBC + l*32);
            float y = 0.f;
            #pragma unroll
            for (int q = 0; q < 4; q++){
                float4 Bv = bc4[q];
                float4 Cv = bc4[4+q];
                h[4*q+0] = h[4*q+0]*ex2f(dtv*A[4*q+0]) + dx*Bv.x;  y += h[4*q+0]*Cv.x;
                h[4*q+1] = h[4*q+1]*ex2f(dtv*A[4*q+1]) + dx*Bv.y;  y += h[4*q+1]*Cv.y;
                h[4*q+2] = h[4*q+2]*ex2f(dtv*A[4*q+2]) + dx*Bv.z;  y += h[4*q+2]*Cv.z;
                h[4*q+3] = h[4*q+3]*ex2f(dtv*A[4*q+3]) + dx*Bv.w;  y += h[4*q+3]*Cv.w;
            }
            ysout[l*DD + dd] = y + Dd*xv;
        }
    }
}

// ---------------- block reduction (sum, sumsq) over 512 threads ------------
__device__ __forceinline__ float2 blockReduce2(float a, float b){
    __shared__ float sa[16], sb[16];
    __shared__ float2 res;
    int lane = threadIdx.x & 31, w = threadIdx.x >> 5;
    #pragma unroll
    for (int o = 16; o; o >>= 1){
        a += __shfl_xor_sync(0xffffffffu, a, o);
        b += __shfl_xor_sync(0xffffffffu, b, o);
    }
    __syncthreads();
    if (lane == 0){ sa[w] = a; sb[w] = b; }
    __syncthreads();
    if (w == 0){
        a = (lane < 16) ? sa[lane] : 0.f;
        b = (lane < 16) ? sb[lane] : 0.f;
        #pragma unroll
        for (int o = 8; o; o >>= 1){
            a += __shfl_xor_sync(0xffffffffu, a, o);
            b += __shfl_xor_sync(0xffffffffu, b, o);
        }
        if (lane == 0){ res.x = a; res.y = b; }
    }
    __syncthreads();
    return res;
}

// ---------------- K7: combine directions + LN + silu(z) gate + pool + LN ---
#define CB_SMEM ((LL*DD + 128)*4)
__global__ void __launch_bounds__(512, 1)
k_combine(const float* __restrict__ og_, const float* __restrict__ ob_,
          const float* __restrict__ ng_, const float* __restrict__ nb_){
    extern __shared__ float sv[];        // 49*512 + mu/rs
    float* smu = sv + LL*DD;             // 49
    float* srs = smu + 56;               // 49
    int s = blockIdx.x, d = threadIdx.x;   // 64 slots, 512 threads
    int b = s >> 1;
    int e = g_topi[s];
    size_t yb = (size_t)(e*BB+b)*KDn*LL*DD;
    #pragma unroll 1
    for (int l = 0; l < LL; l++){
        int i = l/7, j = l - 7*i;
        int lv = j*7 + i;
        float v = g_ys[yb + (0*LL + l       )*DD + d]
                + g_ys[yb + (1*LL + (48-l)  )*DD + d]
                + g_ys[yb + (2*LL + lv      )*DD + d]
                + g_ys[yb + (3*LL + (48-lv) )*DD + d];
        sv[l*DD + d] = v;
    }
    __syncthreads();
    int w = d >> 5, lane = d & 31;
    for (int l = w; l < LL; l += 16){
        float a = 0.f, s2 = 0.f;
        #pragma unroll
        for (int jj = 0; jj < 16; jj++){
            float xv = sv[l*DD + lane + 32*jj];
            a += xv; s2 += xv*xv;
        }
        #pragma unroll
        for (int o = 16; o; o >>= 1){
            a  += __shfl_xor_sync(0xffffffffu, a, o);
            s2 += __shfl_xor_sync(0xffffffffu, s2, o);
        }
        if (lane == 0){
            float mu = a*(1.f/512.f);
            float var = s2*(1.f/512.f) - mu*mu;
            smu[l] = mu;
            srs[l] = rsqrtf(var + 1e-5f);
        }
    }
    __syncthreads();
    float og = og_[e*DD+d], ob = ob_[e*DD+d];
    const float* zrow = g_z + (size_t)(e*BB+b)*LL*DD + d;
    float pooled = 0.f;
    #pragma unroll 7
    for (int l = 0; l < LL; l++){
        float v = sv[l*DD + d];
        float yn = (v - smu[l])*srs[l]*og + ob;
        float z = zrow[l*DD];
        pooled += yn * (z / (1.f + __expf(-z)));
    }
    pooled *= (1.f/49.f);
    float2 ss = blockReduce2(pooled, pooled*pooled);
    float mu = ss.x*(1.f/512.f);
    float var = ss.y*(1.f/512.f) - mu*mu;
    float rs = rsqrtf(var + 1e-5f);
    g_allout[s*DD + d] = (pooled - mu)*rs*ng_[e*DD+d] + nb_[e*DD+d];
}

// ---------------- K8: mixture + aux loss output -----------------------------
__global__ void k_mix(float* __restrict__ out, int out_size){
    int b = blockIdx.x, d = threadIdx.x;
    float v0 = g_topv[b*2], v1 = g_topv[b*2+1];
    out[b*DD + d] = v0*g_allout[(b*2)*DD + d] + v1*g_allout[(b*2+1)*DD + d];
    if (b == 0 && d == 0 && out_size > BB*DD) out[BB*DD] = g_aux;
}

// ---------------- launch ----------------------------------------------------
extern "C" void kernel_launch(void* const* d_in, const int* in_sizes, int n_in,
                              void* d_out, int out_size){
    const float* x    = (const float*)d_in[0];
    const float* wg   = (const float*)d_in[1];
    const float* bg   = (const float*)d_in[2];
    const float* ipw  = (const float*)d_in[3];
    const float* ipb  = (const float*)d_in[4];
    const float* cw   = (const float*)d_in[5];
    const float* cb   = (const float*)d_in[6];
    const float* xpw  = (const float*)d_in[7];
    const float* dtw  = (const float*)d_in[8];
    const float* dtb  = (const float*)d_in[9];
    const float* alog = (const float*)d_in[10];
    const float* ds   = (const float*)d_in[11];
    const float* ong  = (const float*)d_in[12];
    const float* onb  = (const float*)d_in[13];
    const float* ng   = (const float*)d_in[14];
    const float* nb   = (const float*)d_in[15];
    float* out = (float*)d_out;

    cudaFuncSetAttribute(k_inproj,   cudaFuncAttributeMaxDynamicSharedMemorySize, IP_SMEM);
    cudaFuncSetAttribute(k_xdblscan, cudaFuncAttributeMaxDynamicSharedMemorySize, XD_SMEM_BYTES);
    cudaFuncSetAttribute(k_combine,  cudaFuncAttributeMaxDynamicSharedMemorySize, CB_SMEM);

    k_gate    <<<32, 512>>>(x, wg, bg);
    k_gatefin <<<1, 32>>>();
    k_inproj  <<<dim3(NSLOT, 2), 256, IP_SMEM>>>(x, ipw, ipb, cw, cb);
    k_xdblscan<<<NSLOT*KDn, 512, XD_SMEM_BYTES>>>(xpw, dtw, dtb, alog, ds);
    k_combine <<<NSLOT, 512, CB_SMEM>>>(ong, onb, ng, nb);
    k_mix     <<<BB, 512>>>(out, out_size);
}